// round 5
// baseline (speedup 1.0000x reference)
#include <cuda_runtime.h>
#include <cuda_bf16.h>
#include <math.h>

#define BB   256      // batch
#define SS   64       // src len
#define TT   20       // tgt len
#define EE   100      // embed dim
#define HH   1024     // hidden
#define VV   32000    // vocab out
#define TD   (TT-1)   // 19 decoder steps
#define KX   (EE+HH)  // 1124

// ---------------- scratch (device globals: allocation-free) ----------------
__device__ float g_gi_e[(size_t)BB*SS*3*HH];      // encoder input gates  [B*S,3H]
__device__ float g_gi_d[(size_t)BB*TD*3*HH];      // decoder input gates  [B*TD,3H]
__device__ float g_gh[(size_t)BB*3*HH];           // per-step hidden gates
__device__ float g_hbuf[2][(size_t)BB*HH];        // ping-pong hidden
__device__ float g_ctx[(size_t)BB*HH];            // encoder context
__device__ float g_x[(size_t)BB*TD*KX];           // decoder concat input
__device__ float g_logits[(size_t)BB*VV];         // per-step logits
__device__ float g_ce[BB];
__device__ float g_loss;

// ---------------- generic GEMM: C[M,N] = A[M,K] @ B[N,K]^T + bias[N] -------
// Requires K % 4 == 0 (true for 100, 1024, 1124).
// Optional row-gather: if gidx != nullptr, A-row m is A[gidx[m]*K : ...]
#define BM 64
#define BN 64
#define BK 16
__global__ __launch_bounds__(256) void gemm_bias(
    const float* __restrict__ A, const int* __restrict__ gidx,
    const float* __restrict__ Bw, const float* __restrict__ bias,
    float* __restrict__ C, int M, int N, int K)
{
    __shared__ float As[BK][BM + 4];
    __shared__ float Bs[BK][BN + 4];
    const int tid = threadIdx.x;
    const int tr = tid >> 4, tc = tid & 15;       // 16x16 thread grid
    const int rowBase = blockIdx.y * BM;
    const int colBase = blockIdx.x * BN;

    // float4 load mapping: 64 rows x 4 chunks (16 k) = 256 threads
    const int lr = tid >> 2;            // 0..63
    const int lk = (tid & 3) * 4;       // 0,4,8,12

    float acc[4][4] = {};

    for (int k0 = 0; k0 < K; k0 += BK) {
        // ---- A tile ----
        {
            int gm = rowBase + lr;
            float4 v = make_float4(0.f, 0.f, 0.f, 0.f);
            if (gm < M) {
                size_t row = gidx ? (size_t)gidx[gm] : (size_t)gm;
                const float* ap = A + row * (size_t)K + k0 + lk;
                if (k0 + lk + 3 < K) {
                    v = *reinterpret_cast<const float4*>(ap);
                } else {
                    if (k0 + lk + 0 < K) v.x = ap[0];
                    if (k0 + lk + 1 < K) v.y = ap[1];
                    if (k0 + lk + 2 < K) v.z = ap[2];
                    if (k0 + lk + 3 < K) v.w = ap[3];
                }
            }
            As[lk + 0][lr] = v.x;
            As[lk + 1][lr] = v.y;
            As[lk + 2][lr] = v.z;
            As[lk + 3][lr] = v.w;
        }
        // ---- B tile ----
        {
            int gn = colBase + lr;
            float4 v = make_float4(0.f, 0.f, 0.f, 0.f);
            if (gn < N) {
                const float* bp = Bw + (size_t)gn * (size_t)K + k0 + lk;
                if (k0 + lk + 3 < K) {
                    v = *reinterpret_cast<const float4*>(bp);
                } else {
                    if (k0 + lk + 0 < K) v.x = bp[0];
                    if (k0 + lk + 1 < K) v.y = bp[1];
                    if (k0 + lk + 2 < K) v.z = bp[2];
                    if (k0 + lk + 3 < K) v.w = bp[3];
                }
            }
            Bs[lk + 0][lr] = v.x;
            Bs[lk + 1][lr] = v.y;
            Bs[lk + 2][lr] = v.z;
            Bs[lk + 3][lr] = v.w;
        }
        __syncthreads();
        #pragma unroll
        for (int kk = 0; kk < BK; kk++) {
            float a[4], b[4];
            #pragma unroll
            for (int i = 0; i < 4; i++) a[i] = As[kk][tr * 4 + i];
            #pragma unroll
            for (int j = 0; j < 4; j++) b[j] = Bs[kk][tc * 4 + j];
            #pragma unroll
            for (int i = 0; i < 4; i++)
                #pragma unroll
                for (int j = 0; j < 4; j++)
                    acc[i][j] = fmaf(a[i], b[j], acc[i][j]);
        }
        __syncthreads();
    }
    #pragma unroll
    for (int i = 0; i < 4; i++) {
        int gm = rowBase + tr * 4 + i;
        if (gm >= M) continue;
        #pragma unroll
        for (int j = 0; j < 4; j++) {
            int gn = colBase + tc * 4 + j;
            if (gn < N)
                C[(size_t)gm * (size_t)N + gn] = acc[i][j] + bias[gn];
        }
    }
}

// ---------------- GRU gate fusion (PyTorch r,z,n order) --------------------
__device__ __forceinline__ float sigf(float x) { return 1.f / (1.f + expf(-x)); }

__global__ void gru_gate(const float* __restrict__ gi, int gi_stride,
                         const float* __restrict__ gh,
                         const float* __restrict__ hin,
                         float* __restrict__ hout,
                         float* __restrict__ ctx,
                         const int* __restrict__ lengths, int step)
{
    int idx = blockIdx.x * blockDim.x + threadIdx.x;
    if (idx >= BB * HH) return;
    int b = idx >> 10, j = idx & (HH - 1);
    const float* gib = gi + (size_t)b * gi_stride;
    const float* ghb = gh + (size_t)b * 3 * HH;
    float ir = gib[j], iz = gib[HH + j], in_ = gib[2 * HH + j];
    float hr = ghb[j], hz = ghb[HH + j], hn = ghb[2 * HH + j];
    float r = sigf(ir + hr);
    float z = sigf(iz + hz);
    float n = tanhf(in_ + r * hn);
    float h2 = (1.f - z) * n + z * hin[idx];
    hout[idx] = h2;
    if (ctx != nullptr && lengths[b] - 1 == step) ctx[idx] = h2;
}

// ---------------- decoder concat input x = [E_dec[tok], context] -----------
__global__ void build_x(const int* __restrict__ targets,
                        const float* __restrict__ Edec,
                        const float* __restrict__ ctx,
                        float* __restrict__ x)
{
    int idx = blockIdx.x * blockDim.x + threadIdx.x;
    const int total = BB * TD * KX;
    if (idx >= total) return;
    int k = idx % KX;
    int rt = idx / KX;
    int t = rt % TD, b = rt / TD;
    float v;
    if (k < EE) {
        int tok = (t == 0) ? 1 : targets[b * TT + t];  // START_IDX = 1
        v = Edec[(size_t)tok * EE + k];
    } else {
        v = ctx[(size_t)b * HH + (k - EE)];
    }
    x[idx] = v;
}

// ---------------- CE via online logsumexp (one block per batch row) --------
__global__ void ce_kernel(const float* __restrict__ logits,
                          const int* __restrict__ targets,
                          int tstep, float* __restrict__ ce)
{
    int b = blockIdx.x;
    const float* row = logits + (size_t)b * VV;
    int tgt = targets[b * TT + tstep + 1];
    float m = -INFINITY, s = 0.f, tlog = 0.f;
    for (int v = threadIdx.x; v < VV; v += blockDim.x) {
        float x = row[v];
        if (v == tgt) tlog = x;
        if (x > m) { s = s * expf(m - x) + 1.f; m = x; }
        else       { s += expf(x - m); }
    }
    __shared__ float sm[256], ss[256], st[256];
    sm[threadIdx.x] = m; ss[threadIdx.x] = s; st[threadIdx.x] = tlog;
    __syncthreads();
    for (int off = 128; off > 0; off >>= 1) {
        if (threadIdx.x < off) {
            float m2 = sm[threadIdx.x + off], s2 = ss[threadIdx.x + off];
            float M2 = fmaxf(sm[threadIdx.x], m2);
            ss[threadIdx.x] = ss[threadIdx.x] * expf(sm[threadIdx.x] - M2)
                            + s2 * expf(m2 - M2);
            sm[threadIdx.x] = M2;
            st[threadIdx.x] += st[threadIdx.x + off];
        }
        __syncthreads();
    }
    if (threadIdx.x == 0)
        ce[b] = (sm[0] + logf(ss[0])) - st[0];
}

__global__ void accum_kernel(const float* __restrict__ ce,
                             const int* __restrict__ targets,
                             int tstep, float* __restrict__ out, int last)
{
    __shared__ float sc[256], sk[256];
    int b = threadIdx.x;
    sc[b] = ce[b];
    sk[b] = (targets[b * TT + tstep + 1] >= 1) ? 1.f : 0.f;
    __syncthreads();
    for (int off = 128; off > 0; off >>= 1) {
        if (b < off) { sc[b] += sc[b + off]; sk[b] += sk[b + off]; }
        __syncthreads();
    }
    if (b == 0) {
        float l = g_loss + (sc[0] / BB) * (sk[0] / BB);
        g_loss = l;
        if (last) out[0] = l / TT;
    }
}

__global__ void zero_loss() { g_loss = 0.f; }

// ---------------- launch ---------------------------------------------------
extern "C" void kernel_launch(void* const* d_in, const int* in_sizes, int n_in,
                              void* d_out, int out_size)
{
    const int*   inputs  = (const int*)  d_in[0];
    const int*   targets = (const int*)  d_in[1];
    const int*   lengths = (const int*)  d_in[2];
    const float* h0      = (const float*)d_in[3];
    const float* Eenc    = (const float*)d_in[4];
    const float* Edec    = (const float*)d_in[5];
    const float* W_ih_e  = (const float*)d_in[6];
    const float* W_hh_e  = (const float*)d_in[7];
    const float* b_ih_e  = (const float*)d_in[8];
    const float* b_hh_e  = (const float*)d_in[9];
    const float* W_ih_d  = (const float*)d_in[10];
    const float* W_hh_d  = (const float*)d_in[11];
    const float* b_ih_d  = (const float*)d_in[12];
    const float* b_hh_d  = (const float*)d_in[13];
    const float* W_fc    = (const float*)d_in[14];
    const float* b_fc    = (const float*)d_in[15];
    float* out = (float*)d_out;

    float *p_gi_e, *p_gi_d, *p_gh, *p_hb, *p_ctx, *p_x, *p_logits, *p_ce;
    cudaGetSymbolAddress((void**)&p_gi_e,   g_gi_e);
    cudaGetSymbolAddress((void**)&p_gi_d,   g_gi_d);
    cudaGetSymbolAddress((void**)&p_gh,     g_gh);
    cudaGetSymbolAddress((void**)&p_hb,     g_hbuf);
    cudaGetSymbolAddress((void**)&p_ctx,    g_ctx);
    cudaGetSymbolAddress((void**)&p_x,      g_x);
    cudaGetSymbolAddress((void**)&p_logits, g_logits);
    cudaGetSymbolAddress((void**)&p_ce,     g_ce);
    float* p_h0b = p_hb;
    float* p_h1b = p_hb + (size_t)BB * HH;

    zero_loss<<<1, 1>>>();

    // Encoder input gates: fused gather(E_enc) GEMM -> [B*S, 3H]
    gemm_bias<<<dim3(3 * HH / BN, (BB * SS) / BM), 256>>>(
        Eenc, inputs, W_ih_e, b_ih_e, p_gi_e, BB * SS, 3 * HH, EE);

    // Encoder recurrence
    const float* hin = h0;
    for (int s = 0; s < SS; s++) {
        gemm_bias<<<dim3(3 * HH / BN, BB / BM), 256>>>(
            hin, nullptr, W_hh_e, b_hh_e, p_gh, BB, 3 * HH, HH);
        float* hout = (s & 1) ? p_h1b : p_h0b;
        gru_gate<<<(BB * HH) / 256, 256>>>(
            p_gi_e + (size_t)s * 3 * HH, SS * 3 * HH, p_gh, hin, hout,
            p_ctx, lengths, s);
        hin = hout;
    }

    // Decoder input gates
    build_x<<<(BB * TD * KX + 255) / 256, 256>>>(targets, Edec, p_ctx, p_x);
    gemm_bias<<<dim3(3 * HH / BN, (BB * TD) / BM), 256>>>(
        p_x, nullptr, W_ih_d, b_ih_d, p_gi_d, BB * TD, 3 * HH, KX);

    // Decoder recurrence + CE
    hin = p_ctx;
    for (int t = 0; t < TD; t++) {
        gemm_bias<<<dim3(3 * HH / BN, BB / BM), 256>>>(
            hin, nullptr, W_hh_d, b_hh_d, p_gh, BB, 3 * HH, HH);
        float* hout = (t & 1) ? p_h1b : p_h0b;
        gru_gate<<<(BB * HH) / 256, 256>>>(
            p_gi_d + (size_t)t * 3 * HH, TD * 3 * HH, p_gh, hin, hout,
            nullptr, nullptr, -1);
        hin = hout;
        gemm_bias<<<dim3(VV / BN, BB / BM), 256>>>(
            hin, nullptr, W_fc, b_fc, p_logits, BB, VV, HH);
        ce_kernel<<<BB, 256>>>(p_logits, targets, t, p_ce);
        accum_kernel<<<1, 256>>>(p_ce, targets, t, out, t == TD - 1);
    }
}

// round 7
// speedup vs baseline: 2.8452x; 2.8452x over previous
#include <cuda_runtime.h>
#include <cuda_bf16.h>
#include <math.h>

#define BB   256      // batch
#define SS   64       // src len
#define TT   20       // tgt len
#define EE   100      // embed dim
#define HH   1024     // hidden
#define VV   32000    // vocab out
#define TD   (TT-1)   // 19 decoder steps
#define KX   (EE+HH)  // 1124

// padded-K for bf16 weight buffers (multiple of 32)
#define KP_E 128
#define KP_H 1024
#define KP_X 1152

// ---------------- scratch (device globals: allocation-free) ----------------
__device__ float g_gi_e[(size_t)BB*SS*3*HH];
__device__ float g_gi_d[(size_t)BB*TD*3*HH];
__device__ float g_gh[(size_t)BB*3*HH];
__device__ float g_hbuf[2][(size_t)BB*HH];
__device__ float g_ctx[(size_t)BB*HH];
__device__ float g_x[(size_t)BB*TD*KX];
__device__ float g_logits[(size_t)BB*VV];
__device__ float g_ce[BB];
__device__ float g_loss;

// bf16 weight buffers (zero-padded to Kp)
__device__ __nv_bfloat16 g_Wihe[(size_t)3*HH*KP_E];
__device__ __nv_bfloat16 g_Whhe[(size_t)3*HH*KP_H];
__device__ __nv_bfloat16 g_Wihd[(size_t)3*HH*KP_X];
__device__ __nv_bfloat16 g_Whhd[(size_t)3*HH*KP_H];
__device__ __nv_bfloat16 g_Wfc [(size_t)VV*KP_H];

// ---------------- fp32 -> bf16 weight conversion with K padding ------------
__global__ void cvt_pad(const float* __restrict__ src,
                        __nv_bfloat16* __restrict__ dst,
                        int N, int K, int Kp)
{
    long long i = (long long)blockIdx.x * blockDim.x + threadIdx.x;
    long long total = (long long)N * Kp;
    if (i >= total) return;
    int n = (int)(i / Kp), k = (int)(i % Kp);
    dst[i] = __float2bfloat16(k < K ? src[(size_t)n * K + k] : 0.f);
}

// ---------------- bf16 tensor-core GEMM: C = A(fp32)[M,K] @ Bw(bf16)[N,Kp]^T + bias
// Requirements: M % 128 == 0, N % 64 == 0, K % 4 == 0, Kp % 32 == 0, Kp >= K.
// Optional row gather on A via gidx.
#define GBM 128
#define GBN 64
#define ASTR 40     // smem row stride (bf16 elems), conflict-free padding
#define BSTR 40

__device__ __forceinline__ void mma16816(float* c, const unsigned* a, const unsigned* b)
{
    asm volatile(
        "mma.sync.aligned.m16n8k16.row.col.f32.bf16.bf16.f32 "
        "{%0,%1,%2,%3}, {%4,%5,%6,%7}, {%8,%9}, {%0,%1,%2,%3};\n"
        : "+f"(c[0]), "+f"(c[1]), "+f"(c[2]), "+f"(c[3])
        : "r"(a[0]), "r"(a[1]), "r"(a[2]), "r"(a[3]), "r"(b[0]), "r"(b[1]));
}

__global__ __launch_bounds__(256) void gemm_bf16(
    const float* __restrict__ A, const int* __restrict__ gidx,
    const __nv_bfloat16* __restrict__ Bw, const float* __restrict__ bias,
    float* __restrict__ C, int M, int N, int K, int Kp)
{
    __shared__ __nv_bfloat16 As[GBM * ASTR];
    __shared__ __nv_bfloat16 Bs[GBN * BSTR];

    const int tid  = threadIdx.x;
    const int lane = tid & 31;
    const int wid  = tid >> 5;
    const int grp  = lane >> 2;        // 0..7
    const int tig  = lane & 3;         // 0..3
    const int warp_m = wid & 3;        // 4 warps along M (32 rows each)
    const int warp_n = wid >> 2;       // 2 warps along N (32 cols each)

    const int rowBase = blockIdx.y * GBM;
    const int colBase = blockIdx.x * GBN;

    // A-tile loader mapping: 256 threads -> 128 rows x 2 halves of 16 k
    const int arow  = tid >> 1;
    const int ahalf = (tid & 1) * 16;
    // B-tile loader mapping: 256 threads -> 64 rows x 4 chunks of 8 k
    const int brow  = tid >> 2;
    const int bkoff = (tid & 3) * 8;

    const int gm = rowBase + arow;
    const size_t asrc_row = gidx ? (size_t)gidx[gm] : (size_t)gm;
    const float* aprow = A + asrc_row * (size_t)K;
    const __nv_bfloat16* bprow = Bw + (size_t)(colBase + brow) * Kp;

    float acc[2][4][4] = {};

    for (int k0 = 0; k0 < Kp; k0 += 32) {
        // ---- load A tile (fp32 -> bf16 on the fly, zero-pad k >= K) ----
        {
            uint2 pk[4];
            #pragma unroll
            for (int q = 0; q < 4; q++) {
                int kb = k0 + ahalf + q * 4;
                float4 v = make_float4(0.f, 0.f, 0.f, 0.f);
                if (kb < K) v = *reinterpret_cast<const float4*>(aprow + kb);
                __nv_bfloat162 lo = __floats2bfloat162_rn(v.x, v.y);
                __nv_bfloat162 hi = __floats2bfloat162_rn(v.z, v.w);
                pk[q].x = *reinterpret_cast<unsigned*>(&lo);
                pk[q].y = *reinterpret_cast<unsigned*>(&hi);
            }
            uint2* dst = reinterpret_cast<uint2*>(&As[arow * ASTR + ahalf]);
            dst[0] = pk[0]; dst[1] = pk[1]; dst[2] = pk[2]; dst[3] = pk[3];
        }
        // ---- load B tile (already bf16, padded; no guards) ----
        {
            uint4 v = *reinterpret_cast<const uint4*>(bprow + k0 + bkoff);
            uint2* d = reinterpret_cast<uint2*>(&Bs[brow * BSTR + bkoff]);
            d[0] = make_uint2(v.x, v.y);
            d[1] = make_uint2(v.z, v.w);
        }
        __syncthreads();

        #pragma unroll
        for (int ks = 0; ks < 32; ks += 16) {
            unsigned afr[2][4], bfr[4][2];
            #pragma unroll
            for (int mt = 0; mt < 2; mt++) {
                const __nv_bfloat16* base =
                    &As[(warp_m * 32 + mt * 16 + grp) * ASTR + ks + tig * 2];
                afr[mt][0] = *reinterpret_cast<const unsigned*>(base);
                afr[mt][1] = *reinterpret_cast<const unsigned*>(base + 8 * ASTR);
                afr[mt][2] = *reinterpret_cast<const unsigned*>(base + 8);
                afr[mt][3] = *reinterpret_cast<const unsigned*>(base + 8 * ASTR + 8);
            }
            #pragma unroll
            for (int nt = 0; nt < 4; nt++) {
                const __nv_bfloat16* base =
                    &Bs[(warp_n * 32 + nt * 8 + grp) * BSTR + ks + tig * 2];
                bfr[nt][0] = *reinterpret_cast<const unsigned*>(base);
                bfr[nt][1] = *reinterpret_cast<const unsigned*>(base + 8);
            }
            #pragma unroll
            for (int mt = 0; mt < 2; mt++)
                #pragma unroll
                for (int nt = 0; nt < 4; nt++)
                    mma16816(acc[mt][nt], afr[mt], bfr[nt]);
        }
        __syncthreads();
    }

    // ---- epilogue ----
    #pragma unroll
    for (int mt = 0; mt < 2; mt++) {
        int r0 = rowBase + warp_m * 32 + mt * 16 + grp;
        #pragma unroll
        for (int nt = 0; nt < 4; nt++) {
            int c0 = colBase + warp_n * 32 + nt * 8 + tig * 2;
            float b0 = bias[c0], b1 = bias[c0 + 1];
            float2 v01 = make_float2(acc[mt][nt][0] + b0, acc[mt][nt][1] + b1);
            float2 v23 = make_float2(acc[mt][nt][2] + b0, acc[mt][nt][3] + b1);
            *reinterpret_cast<float2*>(&C[(size_t)r0 * N + c0]) = v01;
            *reinterpret_cast<float2*>(&C[(size_t)(r0 + 8) * N + c0]) = v23;
        }
    }
}

// ---------------- GRU gate fusion (PyTorch r,z,n order) --------------------
__device__ __forceinline__ float sigf(float x) { return 1.f / (1.f + expf(-x)); }

__global__ void gru_gate(const float* __restrict__ gi, int gi_stride,
                         const float* __restrict__ gh,
                         const float* __restrict__ hin,
                         float* __restrict__ hout,
                         float* __restrict__ ctx,
                         const int* __restrict__ lengths, int step)
{
    int idx = blockIdx.x * blockDim.x + threadIdx.x;
    if (idx >= BB * HH) return;
    int b = idx >> 10, j = idx & (HH - 1);
    const float* gib = gi + (size_t)b * gi_stride;
    const float* ghb = gh + (size_t)b * 3 * HH;
    float ir = gib[j], iz = gib[HH + j], in_ = gib[2 * HH + j];
    float hr = ghb[j], hz = ghb[HH + j], hn = ghb[2 * HH + j];
    float r = sigf(ir + hr);
    float z = sigf(iz + hz);
    float n = tanhf(in_ + r * hn);
    float h2 = (1.f - z) * n + z * hin[idx];
    hout[idx] = h2;
    if (ctx != nullptr && lengths[b] - 1 == step) ctx[idx] = h2;
}

// ---------------- decoder concat input x = [E_dec[tok], context] -----------
__global__ void build_x(const int* __restrict__ targets,
                        const float* __restrict__ Edec,
                        const float* __restrict__ ctx,
                        float* __restrict__ x)
{
    int idx = blockIdx.x * blockDim.x + threadIdx.x;
    const int total = BB * TD * KX;
    if (idx >= total) return;
    int k = idx % KX;
    int rt = idx / KX;
    int t = rt % TD, b = rt / TD;
    float v;
    if (k < EE) {
        int tok = (t == 0) ? 1 : targets[b * TT + t];  // START_IDX = 1
        v = Edec[(size_t)tok * EE + k];
    } else {
        v = ctx[(size_t)b * HH + (k - EE)];
    }
    x[idx] = v;
}

// ---------------- CE via online logsumexp (one block per batch row) --------
__global__ void ce_kernel(const float* __restrict__ logits,
                          const int* __restrict__ targets,
                          int tstep, float* __restrict__ ce)
{
    int b = blockIdx.x;
    const float* row = logits + (size_t)b * VV;
    int tgt = targets[b * TT + tstep + 1];
    float m = -INFINITY, s = 0.f, tlog = 0.f;
    for (int v = threadIdx.x; v < VV; v += blockDim.x) {
        float x = row[v];
        if (v == tgt) tlog = x;
        if (x > m) { s = s * expf(m - x) + 1.f; m = x; }
        else       { s += expf(x - m); }
    }
    __shared__ float sm[256], ss[256], st[256];
    sm[threadIdx.x] = m; ss[threadIdx.x] = s; st[threadIdx.x] = tlog;
    __syncthreads();
    for (int off = 128; off > 0; off >>= 1) {
        if (threadIdx.x < off) {
            float m2 = sm[threadIdx.x + off], s2 = ss[threadIdx.x + off];
            float M2 = fmaxf(sm[threadIdx.x], m2);
            ss[threadIdx.x] = ss[threadIdx.x] * expf(sm[threadIdx.x] - M2)
                            + s2 * expf(m2 - M2);
            sm[threadIdx.x] = M2;
            st[threadIdx.x] += st[threadIdx.x + off];
        }
        __syncthreads();
    }
    if (threadIdx.x == 0)
        ce[b] = (sm[0] + logf(ss[0])) - st[0];
}

__global__ void accum_kernel(const float* __restrict__ ce,
                             const int* __restrict__ targets,
                             int tstep, float* __restrict__ out, int last)
{
    __shared__ float sc[256], sk[256];
    int b = threadIdx.x;
    sc[b] = ce[b];
    sk[b] = (targets[b * TT + tstep + 1] >= 1) ? 1.f : 0.f;
    __syncthreads();
    for (int off = 128; off > 0; off >>= 1) {
        if (b < off) { sc[b] += sc[b + off]; sk[b] += sk[b + off]; }
        __syncthreads();
    }
    if (b == 0) {
        float l = g_loss + (sc[0] / BB) * (sk[0] / BB);
        g_loss = l;
        if (last) out[0] = l / TT;
    }
}

__global__ void zero_loss() { g_loss = 0.f; }

// ---------------- launch ---------------------------------------------------
extern "C" void kernel_launch(void* const* d_in, const int* in_sizes, int n_in,
                              void* d_out, int out_size)
{
    const int*   inputs  = (const int*)  d_in[0];
    const int*   targets = (const int*)  d_in[1];
    const int*   lengths = (const int*)  d_in[2];
    const float* h0      = (const float*)d_in[3];
    const float* Eenc    = (const float*)d_in[4];
    const float* Edec    = (const float*)d_in[5];
    const float* W_ih_e  = (const float*)d_in[6];
    const float* W_hh_e  = (const float*)d_in[7];
    const float* b_ih_e  = (const float*)d_in[8];
    const float* b_hh_e  = (const float*)d_in[9];
    const float* W_ih_d  = (const float*)d_in[10];
    const float* W_hh_d  = (const float*)d_in[11];
    const float* b_ih_d  = (const float*)d_in[12];
    const float* b_hh_d  = (const float*)d_in[13];
    const float* W_fc    = (const float*)d_in[14];
    const float* b_fc    = (const float*)d_in[15];
    float* out = (float*)d_out;

    float *p_gi_e, *p_gi_d, *p_gh, *p_hb, *p_ctx, *p_x, *p_logits, *p_ce;
    __nv_bfloat16 *p_Wihe, *p_Whhe, *p_Wihd, *p_Whhd, *p_Wfc;
    cudaGetSymbolAddress((void**)&p_gi_e,   g_gi_e);
    cudaGetSymbolAddress((void**)&p_gi_d,   g_gi_d);
    cudaGetSymbolAddress((void**)&p_gh,     g_gh);
    cudaGetSymbolAddress((void**)&p_hb,     g_hbuf);
    cudaGetSymbolAddress((void**)&p_ctx,    g_ctx);
    cudaGetSymbolAddress((void**)&p_x,      g_x);
    cudaGetSymbolAddress((void**)&p_logits, g_logits);
    cudaGetSymbolAddress((void**)&p_ce,     g_ce);
    cudaGetSymbolAddress((void**)&p_Wihe,   g_Wihe);
    cudaGetSymbolAddress((void**)&p_Whhe,   g_Whhe);
    cudaGetSymbolAddress((void**)&p_Wihd,   g_Wihd);
    cudaGetSymbolAddress((void**)&p_Whhd,   g_Whhd);
    cudaGetSymbolAddress((void**)&p_Wfc,    g_Wfc);
    float* p_h0b = p_hb;
    float* p_h1b = p_hb + (size_t)BB * HH;

    zero_loss<<<1, 1>>>();

    // ---- one-shot weight conversions (inside graph; ~30us total) ----
    {
        long long n;
        n = (long long)3 * HH * KP_E;
        cvt_pad<<<(unsigned)((n + 255) / 256), 256>>>(W_ih_e, p_Wihe, 3 * HH, EE, KP_E);
        n = (long long)3 * HH * KP_H;
        cvt_pad<<<(unsigned)((n + 255) / 256), 256>>>(W_hh_e, p_Whhe, 3 * HH, HH, KP_H);
        n = (long long)3 * HH * KP_X;
        cvt_pad<<<(unsigned)((n + 255) / 256), 256>>>(W_ih_d, p_Wihd, 3 * HH, KX, KP_X);
        n = (long long)3 * HH * KP_H;
        cvt_pad<<<(unsigned)((n + 255) / 256), 256>>>(W_hh_d, p_Whhd, 3 * HH, HH, KP_H);
        n = (long long)VV * KP_H;
        cvt_pad<<<(unsigned)((n + 255) / 256), 256>>>(W_fc, p_Wfc, VV, HH, KP_H);
    }

    // Encoder input gates: fused gather(E_enc) GEMM -> [B*S, 3H]
    gemm_bf16<<<dim3(3 * HH / GBN, (BB * SS) / GBM), 256>>>(
        Eenc, inputs, p_Wihe, b_ih_e, p_gi_e, BB * SS, 3 * HH, EE, KP_E);

    // Encoder recurrence
    const float* hin = h0;
    for (int s = 0; s < SS; s++) {
        gemm_bf16<<<dim3(3 * HH / GBN, BB / GBM), 256>>>(
            hin, nullptr, p_Whhe, b_hh_e, p_gh, BB, 3 * HH, HH, KP_H);
        float* hout = (s & 1) ? p_h1b : p_h0b;
        gru_gate<<<(BB * HH) / 256, 256>>>(
            p_gi_e + (size_t)s * 3 * HH, SS * 3 * HH, p_gh, hin, hout,
            p_ctx, lengths, s);
        hin = hout;
    }

    // Decoder input gates
    build_x<<<(BB * TD * KX + 255) / 256, 256>>>(targets, Edec, p_ctx, p_x);
    gemm_bf16<<<dim3(3 * HH / GBN, (BB * TD) / GBM), 256>>>(
        p_x, nullptr, p_Wihd, b_ih_d, p_gi_d, BB * TD, 3 * HH, KX, KP_X);

    // Decoder recurrence + CE
    hin = p_ctx;
    for (int t = 0; t < TD; t++) {
        gemm_bf16<<<dim3(3 * HH / GBN, BB / GBM), 256>>>(
            hin, nullptr, p_Whhd, b_hh_d, p_gh, BB, 3 * HH, HH, KP_H);
        float* hout = (t & 1) ? p_h1b : p_h0b;
        gru_gate<<<(BB * HH) / 256, 256>>>(
            p_gi_d + (size_t)t * 3 * HH, TD * 3 * HH, p_gh, hin, hout,
            nullptr, nullptr, -1);
        hin = hout;
        gemm_bf16<<<dim3(VV / GBN, BB / GBM), 256>>>(
            hin, nullptr, p_Wfc, b_fc, p_logits, BB, VV, HH, KP_H);
        ce_kernel<<<BB, 256>>>(p_logits, targets, t, p_ce);
        accum_kernel<<<1, 256>>>(p_ce, targets, t, out, t == TD - 1);
    }
}

// round 9
// speedup vs baseline: 5.5434x; 1.9483x over previous
#include <cuda_runtime.h>
#include <cuda_bf16.h>
#include <math.h>

#define BB   256
#define SS   64
#define TT   20
#define EE   100
#define HH   1024
#define VV   32000
#define VIN  32000
#define TD   (TT-1)
#define KX   (EE+HH)

#define KP_E 128
#define KP_H 1024
#define KP_X 1152

// ---------------- fp32 scratch --------------------------------------------
__device__ float g_gi_e[(size_t)BB*SS*3*HH];
__device__ float g_gi_d[(size_t)BB*TD*3*HH];
__device__ float g_gh[(size_t)BB*3*HH];
__device__ float g_hbuf[2][(size_t)BB*HH];
__device__ float g_ctx[(size_t)BB*HH];
__device__ float g_sumexp[BB];
__device__ float g_tgtlog[BB];
__device__ float g_loss;

// ---------------- bf16 buffers --------------------------------------------
__device__ __nv_bfloat16 g_hbf[2][(size_t)BB*HH];
__device__ __nv_bfloat16 g_h0bf[(size_t)BB*HH];
__device__ __nv_bfloat16 g_ctxbf[(size_t)BB*HH];
__device__ __nv_bfloat16 g_xbf[(size_t)BB*TD*KP_X];
__device__ __nv_bfloat16 g_Eencbf[(size_t)VIN*KP_E];
__device__ __nv_bfloat16 g_Wihe[(size_t)3*HH*KP_E];
__device__ __nv_bfloat16 g_Whhe[(size_t)3*HH*KP_H];
__device__ __nv_bfloat16 g_Wihd[(size_t)3*HH*KP_X];
__device__ __nv_bfloat16 g_Whhd[(size_t)3*HH*KP_H];
__device__ __nv_bfloat16 g_Wfc [(size_t)VV*KP_H];

// ---------------- fp32 -> bf16 conversion with K padding -------------------
__global__ void cvt_pad(const float* __restrict__ src,
                        __nv_bfloat16* __restrict__ dst,
                        int N, int K, int Kp)
{
    long long i = (long long)blockIdx.x * blockDim.x + threadIdx.x;
    long long total = (long long)N * Kp;
    if (i >= total) return;
    int n = (int)(i / Kp), k = (int)(i % Kp);
    dst[i] = __float2bfloat16(k < K ? src[(size_t)n * K + k] : 0.f);
}

// ---------------- init -----------------------------------------------------
__global__ void init_k()
{
    g_sumexp[threadIdx.x] = 0.f;
    if (threadIdx.x == 0) g_loss = 0.f;
}

// ---------------- tensor-core GEMM (cp.async double-buffered) --------------
// C[M,N] = A(bf16)[M,Kp] @ Bw(bf16)[N,Kp]^T + bias
// M % 128 == 0, N % (16*NT) == 0, Kp % 32 == 0. Optional row gather on A.
// CE=true: fused cross-entropy partial sums instead of writing C.
#define STR 56   // smem row stride in bf16 elems (112 B): 16B-aligned, conflict-free

__device__ __forceinline__ void cpa16(void* s, const void* g)
{
    unsigned sa = (unsigned)__cvta_generic_to_shared(s);
    asm volatile("cp.async.cg.shared.global [%0], [%1], 16;\n" :: "r"(sa), "l"(g));
}

__device__ __forceinline__ void mma16816(float* c, const unsigned* a, const unsigned* b)
{
    asm volatile(
        "mma.sync.aligned.m16n8k16.row.col.f32.bf16.bf16.f32 "
        "{%0,%1,%2,%3}, {%4,%5,%6,%7}, {%8,%9}, {%0,%1,%2,%3};\n"
        : "+f"(c[0]), "+f"(c[1]), "+f"(c[2]), "+f"(c[3])
        : "r"(a[0]), "r"(a[1]), "r"(a[2]), "r"(a[3]), "r"(b[0]), "r"(b[1]));
}

template<int NT, bool CE>
__global__ __launch_bounds__(256) void gemm_tc(
    const __nv_bfloat16* __restrict__ A, const int* __restrict__ gidx,
    const __nv_bfloat16* __restrict__ Bw, const float* __restrict__ bias,
    float* __restrict__ C, int M, int N, int Kp,
    const int* __restrict__ targets, int tstep)
{
    constexpr int BN = 16 * NT;
    __shared__ __nv_bfloat16 sm[2][(128 + BN) * STR];

    const int tid  = threadIdx.x;
    const int lane = tid & 31;
    const int wid  = tid >> 5;
    const int grp  = lane >> 2;
    const int tig  = lane & 3;
    const int warp_m = wid & 3;     // 4 warps x 32 rows
    const int warp_n = wid >> 2;    // 2 warps x (8*NT) cols

    const int rowBase = blockIdx.y * 128;
    const int colBase = blockIdx.x * BN;

    // A loader: 128 rows x 4 chunks(16B) = 512 tasks, 2 per thread
    const int ar0 = tid >> 2, ach = tid & 3;
    const int ar1 = ar0 + 64;
    const size_t sr0 = gidx ? (size_t)gidx[rowBase + ar0] : (size_t)(rowBase + ar0);
    const size_t sr1 = gidx ? (size_t)gidx[rowBase + ar1] : (size_t)(rowBase + ar1);
    const __nv_bfloat16* ag0 = A + sr0 * (size_t)Kp + ach * 8;
    const __nv_bfloat16* ag1 = A + sr1 * (size_t)Kp + ach * 8;
    const int aoff0 = ar0 * STR + ach * 8;
    const int aoff1 = ar1 * STR + ach * 8;
    // B loader: BN rows x 4 chunks
    const bool bact = tid < BN * 4;
    const int br = tid >> 2, bch = tid & 3;
    const __nv_bfloat16* bg = Bw + (size_t)(colBase + br) * Kp + bch * 8;
    const int boff = 128 * STR + br * STR + bch * 8;

    float acc[2][NT][4] = {};

    auto issue = [&](int st, int k0) {
        cpa16(&sm[st][aoff0], ag0 + k0);
        cpa16(&sm[st][aoff1], ag1 + k0);
        if (bact) cpa16(&sm[st][boff], bg + k0);
        asm volatile("cp.async.commit_group;\n");
    };

    const int niter = Kp / 32;
    issue(0, 0);
    for (int it = 0; it < niter; it++) {
        if (it + 1 < niter) {
            issue((it + 1) & 1, (it + 1) * 32);
            asm volatile("cp.async.wait_group 1;\n");
        } else {
            asm volatile("cp.async.wait_group 0;\n");
        }
        __syncthreads();
        const __nv_bfloat16* As = sm[it & 1];
        const __nv_bfloat16* Bs = sm[it & 1] + 128 * STR;

        #pragma unroll
        for (int ks = 0; ks < 32; ks += 16) {
            unsigned afr[2][4], bfr[NT][2];
            #pragma unroll
            for (int mt = 0; mt < 2; mt++) {
                const __nv_bfloat16* base =
                    &As[(warp_m * 32 + mt * 16 + grp) * STR + ks + tig * 2];
                afr[mt][0] = *reinterpret_cast<const unsigned*>(base);
                afr[mt][1] = *reinterpret_cast<const unsigned*>(base + 8 * STR);
                afr[mt][2] = *reinterpret_cast<const unsigned*>(base + 8);
                afr[mt][3] = *reinterpret_cast<const unsigned*>(base + 8 * STR + 8);
            }
            #pragma unroll
            for (int nt = 0; nt < NT; nt++) {
                const __nv_bfloat16* base =
                    &Bs[(warp_n * (NT * 8) + nt * 8 + grp) * STR + ks + tig * 2];
                bfr[nt][0] = *reinterpret_cast<const unsigned*>(base);
                bfr[nt][1] = *reinterpret_cast<const unsigned*>(base + 8);
            }
            #pragma unroll
            for (int mt = 0; mt < 2; mt++)
                #pragma unroll
                for (int nt = 0; nt < NT; nt++)
                    mma16816(acc[mt][nt], afr[mt], bfr[nt]);
        }
        __syncthreads();
    }

    if (!CE) {
        #pragma unroll
        for (int mt = 0; mt < 2; mt++) {
            int r0 = rowBase + warp_m * 32 + mt * 16 + grp;
            #pragma unroll
            for (int nt = 0; nt < NT; nt++) {
                int c0 = colBase + warp_n * (NT * 8) + nt * 8 + tig * 2;
                float b0 = bias[c0], b1 = bias[c0 + 1];
                float2 v01 = make_float2(acc[mt][nt][0] + b0, acc[mt][nt][1] + b1);
                float2 v23 = make_float2(acc[mt][nt][2] + b0, acc[mt][nt][3] + b1);
                *reinterpret_cast<float2*>(&C[(size_t)r0 * N + c0]) = v01;
                *reinterpret_cast<float2*>(&C[(size_t)(r0 + 8) * N + c0]) = v23;
            }
        }
    } else {
        // fused CE partials: logits bounded well below exp-overflow, no max shift
        float rs[2][2] = {{0.f, 0.f}, {0.f, 0.f}};
        #pragma unroll
        for (int mt = 0; mt < 2; mt++) {
            int r0 = rowBase + warp_m * 32 + mt * 16 + grp;
            int tg0 = targets[r0 * TT + tstep + 1];
            int tg1 = targets[(r0 + 8) * TT + tstep + 1];
            #pragma unroll
            for (int nt = 0; nt < NT; nt++) {
                int c0 = colBase + warp_n * (NT * 8) + nt * 8 + tig * 2;
                float b0 = bias[c0], b1 = bias[c0 + 1];
                float v0 = acc[mt][nt][0] + b0, v1 = acc[mt][nt][1] + b1;
                float v2 = acc[mt][nt][2] + b0, v3 = acc[mt][nt][3] + b1;
                rs[mt][0] += expf(v0) + expf(v1);
                rs[mt][1] += expf(v2) + expf(v3);
                if (c0 == tg0)     g_tgtlog[r0] = v0;
                if (c0 + 1 == tg0) g_tgtlog[r0] = v1;
                if (c0 == tg1)     g_tgtlog[r0 + 8] = v2;
                if (c0 + 1 == tg1) g_tgtlog[r0 + 8] = v3;
            }
        }
        #pragma unroll
        for (int mt = 0; mt < 2; mt++)
            #pragma unroll
            for (int h = 0; h < 2; h++) {
                float s = rs[mt][h];
                s += __shfl_xor_sync(0xffffffffu, s, 1);
                s += __shfl_xor_sync(0xffffffffu, s, 2);
                if (tig == 0)
                    atomicAdd(&g_sumexp[rowBase + warp_m * 32 + mt * 16 + grp + h * 8], s);
            }
    }
}

// ---------------- GRU gate fusion (float4, emits fp32 + bf16) --------------
__device__ __forceinline__ float sigf(float x) { return 1.f / (1.f + expf(-x)); }

__global__ void gru_gate(const float* __restrict__ gi, int gi_stride,
                         const float* __restrict__ gh,
                         const float* __restrict__ hin,
                         float* __restrict__ hout,
                         __nv_bfloat16* __restrict__ houtbf,
                         float* __restrict__ ctx,
                         __nv_bfloat16* __restrict__ ctxbf,
                         const int* __restrict__ lengths, int step)
{
    int idx = blockIdx.x * blockDim.x + threadIdx.x;   // BB*HH/4 threads
    int b = idx >> 8;
    int j = (idx & 255) * 4;
    const float* gib = gi + (size_t)b * gi_stride + j;
    const float* ghb = gh + (size_t)b * 3 * HH + j;
    float4 ir = *(const float4*)gib;
    float4 iz = *(const float4*)(gib + HH);
    float4 in_ = *(const float4*)(gib + 2 * HH);
    float4 hr = *(const float4*)ghb;
    float4 hz = *(const float4*)(ghb + HH);
    float4 hn = *(const float4*)(ghb + 2 * HH);
    float4 hp = *(const float4*)(hin + (size_t)b * HH + j);
    float4 o;
    {
        float r = sigf(ir.x + hr.x), z = sigf(iz.x + hz.x);
        o.x = (1.f - z) * tanhf(in_.x + r * hn.x) + z * hp.x;
    }
    {
        float r = sigf(ir.y + hr.y), z = sigf(iz.y + hz.y);
        o.y = (1.f - z) * tanhf(in_.y + r * hn.y) + z * hp.y;
    }
    {
        float r = sigf(ir.z + hr.z), z = sigf(iz.z + hz.z);
        o.z = (1.f - z) * tanhf(in_.z + r * hn.z) + z * hp.z;
    }
    {
        float r = sigf(ir.w + hr.w), z = sigf(iz.w + hz.w);
        o.w = (1.f - z) * tanhf(in_.w + r * hn.w) + z * hp.w;
    }
    *(float4*)(hout + (size_t)b * HH + j) = o;
    __nv_bfloat162 p0 = __floats2bfloat162_rn(o.x, o.y);
    __nv_bfloat162 p1 = __floats2bfloat162_rn(o.z, o.w);
    uint2 pk = make_uint2(*reinterpret_cast<unsigned*>(&p0),
                          *reinterpret_cast<unsigned*>(&p1));
    *(uint2*)(houtbf + (size_t)b * HH + j) = pk;
    if (ctx != nullptr && lengths[b] - 1 == step) {
        *(float4*)(ctx + (size_t)b * HH + j) = o;
        *(uint2*)(ctxbf + (size_t)b * HH + j) = pk;
    }
}

// ---------------- decoder concat input (bf16, zero-padded to KP_X) ---------
__global__ void build_x(const int* __restrict__ targets,
                        const float* __restrict__ Edec,
                        const float* __restrict__ ctx,
                        __nv_bfloat16* __restrict__ xbf)
{
    int idx = blockIdx.x * blockDim.x + threadIdx.x;
    const int total = BB * TD * KP_X;
    if (idx >= total) return;
    int k = idx % KP_X;
    int rt = idx / KP_X;
    int t = rt % TD, b = rt / TD;
    float v = 0.f;
    if (k < EE) {
        int tok = (t == 0) ? 1 : targets[b * TT + t];
        v = Edec[(size_t)tok * EE + k];
    } else if (k < KX) {
        v = ctx[(size_t)b * HH + (k - EE)];
    }
    xbf[idx] = __float2bfloat16(v);
}

// ---------------- per-step CE finalize + loss accumulate -------------------
__global__ void ce_finalize(const int* __restrict__ targets, int tstep,
                            float* __restrict__ out, int last)
{
    int b = threadIdx.x;
    float ce = logf(g_sumexp[b]) - g_tgtlog[b];
    g_sumexp[b] = 0.f;   // reset for next step
    float mk = (targets[b * TT + tstep + 1] >= 1) ? 1.f : 0.f;
    __shared__ float sc[256], sk[256];
    sc[b] = ce; sk[b] = mk;
    __syncthreads();
    for (int o = 128; o > 0; o >>= 1) {
        if (b < o) { sc[b] += sc[b + o]; sk[b] += sk[b + o]; }
        __syncthreads();
    }
    if (b == 0) {
        float l = g_loss + (sc[0] / BB) * (sk[0] / BB);
        g_loss = l;
        if (last) out[0] = l / TT;
    }
}

// ---------------- launch ---------------------------------------------------
extern "C" void kernel_launch(void* const* d_in, const int* in_sizes, int n_in,
                              void* d_out, int out_size)
{
    const int*   inputs  = (const int*)  d_in[0];
    const int*   targets = (const int*)  d_in[1];
    const int*   lengths = (const int*)  d_in[2];
    const float* h0      = (const float*)d_in[3];
    const float* Eenc    = (const float*)d_in[4];
    const float* Edec    = (const float*)d_in[5];
    const float* W_ih_e  = (const float*)d_in[6];
    const float* W_hh_e  = (const float*)d_in[7];
    const float* b_ih_e  = (const float*)d_in[8];
    const float* b_hh_e  = (const float*)d_in[9];
    const float* W_ih_d  = (const float*)d_in[10];
    const float* W_hh_d  = (const float*)d_in[11];
    const float* b_ih_d  = (const float*)d_in[12];
    const float* b_hh_d  = (const float*)d_in[13];
    const float* W_fc    = (const float*)d_in[14];
    const float* b_fc    = (const float*)d_in[15];
    float* out = (float*)d_out;

    float *p_gi_e, *p_gi_d, *p_gh, *p_hb, *p_ctx;
    __nv_bfloat16 *p_Wihe, *p_Whhe, *p_Wihd, *p_Whhd, *p_Wfc;
    __nv_bfloat16 *p_hbf, *p_h0bf, *p_ctxbf, *p_xbf, *p_Eencbf;
    cudaGetSymbolAddress((void**)&p_gi_e,   g_gi_e);
    cudaGetSymbolAddress((void**)&p_gi_d,   g_gi_d);
    cudaGetSymbolAddress((void**)&p_gh,     g_gh);
    cudaGetSymbolAddress((void**)&p_hb,     g_hbuf);
    cudaGetSymbolAddress((void**)&p_ctx,    g_ctx);
    cudaGetSymbolAddress((void**)&p_Wihe,   g_Wihe);
    cudaGetSymbolAddress((void**)&p_Whhe,   g_Whhe);
    cudaGetSymbolAddress((void**)&p_Wihd,   g_Wihd);
    cudaGetSymbolAddress((void**)&p_Whhd,   g_Whhd);
    cudaGetSymbolAddress((void**)&p_Wfc,    g_Wfc);
    cudaGetSymbolAddress((void**)&p_hbf,    g_hbf);
    cudaGetSymbolAddress((void**)&p_h0bf,   g_h0bf);
    cudaGetSymbolAddress((void**)&p_ctxbf,  g_ctxbf);
    cudaGetSymbolAddress((void**)&p_xbf,    g_xbf);
    cudaGetSymbolAddress((void**)&p_Eencbf, g_Eencbf);
    float* p_h0b = p_hb;
    float* p_h1b = p_hb + (size_t)BB * HH;
    __nv_bfloat16* p_hbf0 = p_hbf;
    __nv_bfloat16* p_hbf1 = p_hbf + (size_t)BB * HH;

    init_k<<<1, 256>>>();

    // one-shot conversions
    {
        long long n;
        n = (long long)3 * HH * KP_E;
        cvt_pad<<<(unsigned)((n + 255) / 256), 256>>>(W_ih_e, p_Wihe, 3 * HH, EE, KP_E);
        n = (long long)3 * HH * KP_H;
        cvt_pad<<<(unsigned)((n + 255) / 256), 256>>>(W_hh_e, p_Whhe, 3 * HH, HH, KP_H);
        n = (long long)3 * HH * KP_X;
        cvt_pad<<<(unsigned)((n + 255) / 256), 256>>>(W_ih_d, p_Wihd, 3 * HH, KX, KP_X);
        n = (long long)3 * HH * KP_H;
        cvt_pad<<<(unsigned)((n + 255) / 256), 256>>>(W_hh_d, p_Whhd, 3 * HH, HH, KP_H);
        n = (long long)VV * KP_H;
        cvt_pad<<<(unsigned)((n + 255) / 256), 256>>>(W_fc, p_Wfc, VV, HH, KP_H);
        n = (long long)VIN * KP_E;
        cvt_pad<<<(unsigned)((n + 255) / 256), 256>>>(Eenc, p_Eencbf, VIN, EE, KP_E);
        n = (long long)BB * HH;
        cvt_pad<<<(unsigned)((n + 255) / 256), 256>>>(h0, p_h0bf, BB, HH, HH);
    }

    // Encoder input gates: gather(E_enc bf16) GEMM -> [B*S, 3H]
    gemm_tc<4, false><<<dim3(3 * HH / 64, (BB * SS) / 128), 256>>>(
        p_Eencbf, inputs, p_Wihe, b_ih_e, p_gi_e, BB * SS, 3 * HH, KP_E,
        nullptr, 0);

    // Encoder recurrence
    const float* hin = h0;
    const __nv_bfloat16* hinbf = p_h0bf;
    for (int s = 0; s < SS; s++) {
        gemm_tc<2, false><<<dim3(3 * HH / 32, BB / 128), 256>>>(
            hinbf, nullptr, p_Whhe, b_hh_e, p_gh, BB, 3 * HH, KP_H, nullptr, 0);
        float* hout = (s & 1) ? p_h1b : p_h0b;
        __nv_bfloat16* houtbf = (s & 1) ? p_hbf1 : p_hbf0;
        gru_gate<<<(BB * HH / 4) / 256, 256>>>(
            p_gi_e + (size_t)s * 3 * HH, SS * 3 * HH, p_gh, hin, hout, houtbf,
            p_ctx, p_ctxbf, lengths, s);
        hin = hout; hinbf = houtbf;
    }

    // Decoder input gates
    build_x<<<(BB * TD * KP_X + 255) / 256, 256>>>(targets, Edec, p_ctx, p_xbf);
    gemm_tc<4, false><<<dim3(3 * HH / 64, (BB * TD) / 128), 256>>>(
        p_xbf, nullptr, p_Wihd, b_ih_d, p_gi_d, BB * TD, 3 * HH, KP_X,
        nullptr, 0);

    // Decoder recurrence + fused FC/CE
    hin = p_ctx; hinbf = p_ctxbf;
    for (int t = 0; t < TD; t++) {
        gemm_tc<2, false><<<dim3(3 * HH / 32, BB / 128), 256>>>(
            hinbf, nullptr, p_Whhd, b_hh_d, p_gh, BB, 3 * HH, KP_H, nullptr, 0);
        float* hout = (t & 1) ? p_h1b : p_h0b;
        __nv_bfloat16* houtbf = (t & 1) ? p_hbf1 : p_hbf0;
        gru_gate<<<(BB * HH / 4) / 256, 256>>>(
            p_gi_d + (size_t)t * 3 * HH, TD * 3 * HH, p_gh, hin, hout, houtbf,
            nullptr, nullptr, nullptr, -1);
        hin = hout; hinbf = houtbf;
        gemm_tc<4, true><<<dim3(VV / 64, BB / 128), 256>>>(
            houtbf, nullptr, p_Wfc, b_fc, nullptr, BB, VV, KP_H,
            targets, t);
        ce_finalize<<<1, 256>>>(targets, t, out, t == TD - 1);
    }
}

// round 13
// speedup vs baseline: 6.5101x; 1.1744x over previous
#include <cuda_runtime.h>
#include <cuda_bf16.h>
#include <cuda_fp16.h>
#include <math.h>

#define BB   256
#define SS   64
#define TT   20
#define EE   100
#define HH   1024
#define VV   32000
#define VIN  32000
#define TD   (TT-1)
#define KX   (EE+HH)

#define KP_E 128
#define KP_H 1024
#define KP_X 1152

#define STR 56          // smem row stride (bf16 elems) = 112B, conflict-free
#define CEOFF 4.0f      // exp offset for f16 sumexp
#define LOG2E 1.4426950408889634f

// ---------------- scratch ---------------------------------------------------
__device__ float g_gi_e[(size_t)BB*SS*3*HH];
__device__ float g_gi_d[(size_t)BB*TD*3*HH];
__device__ float g_hbuf[2][(size_t)BB*HH];
__device__ float g_ctx[(size_t)BB*HH];
__device__ float g_sumexp2[(size_t)TD*BB];
__device__ float g_tgtlog2[(size_t)TD*BB];

__device__ __nv_bfloat16 g_hbf[2][(size_t)BB*HH];
__device__ __nv_bfloat16 g_h0bf[(size_t)BB*HH];
__device__ __nv_bfloat16 g_ctxbf[(size_t)BB*HH];
__device__ __nv_bfloat16 g_xbf[(size_t)BB*TD*KP_X];
__device__ __nv_bfloat16 g_Eencbf[(size_t)VIN*KP_E];
__device__ __nv_bfloat16 g_Wihe[(size_t)3*HH*KP_E];
__device__ __nv_bfloat16 g_WhheP[(size_t)3*HH*KP_H];   // gate-interleave permuted
__device__ __nv_bfloat16 g_Wihd[(size_t)3*HH*KP_X];
__device__ __nv_bfloat16 g_WhhdP[(size_t)3*HH*KP_H];   // gate-interleave permuted
__device__ __nv_bfloat16 g_Wfc [(size_t)VV*KP_H];

// ---------------- helpers ---------------------------------------------------
__device__ __forceinline__ void cpa16(void* s, const void* g)
{
    unsigned sa = (unsigned)__cvta_generic_to_shared(s);
    asm volatile("cp.async.cg.shared.global [%0], [%1], 16;\n" :: "r"(sa), "l"(g));
}
__device__ __forceinline__ void mma16816(float* c, const unsigned* a, const unsigned* b)
{
    asm volatile(
        "mma.sync.aligned.m16n8k16.row.col.f32.bf16.bf16.f32 "
        "{%0,%1,%2,%3}, {%4,%5,%6,%7}, {%8,%9}, {%0,%1,%2,%3};\n"
        : "+f"(c[0]), "+f"(c[1]), "+f"(c[2]), "+f"(c[3])
        : "r"(a[0]), "r"(a[1]), "r"(a[2]), "r"(a[3]), "r"(b[0]), "r"(b[1]));
}
__device__ __forceinline__ float tanhapx(float x)
{
    float y; asm("tanh.approx.f32 %0, %1;" : "=f"(y) : "f"(x)); return y;
}
__device__ __forceinline__ float sigapx(float x) { return 0.5f * tanhapx(0.5f * x) + 0.5f; }

// ---------------- conversions ----------------------------------------------
__global__ void cvt_pad4(const float* __restrict__ src,
                         __nv_bfloat16* __restrict__ dst,
                         int N, int K, int Kp)
{
    long long i4 = (long long)blockIdx.x * blockDim.x + threadIdx.x;
    long long total = (long long)N * (Kp / 4);
    if (i4 >= total) return;
    int n = (int)(i4 / (Kp / 4));
    int k = (int)(i4 % (Kp / 4)) * 4;
    const float* s = src + (size_t)n * K + k;
    float4 v = make_float4(0.f, 0.f, 0.f, 0.f);
    if (k + 3 < K) v = *reinterpret_cast<const float4*>(s);
    else {
        if (k     < K) v.x = s[0];
        if (k + 1 < K) v.y = s[1];
        if (k + 2 < K) v.z = s[2];
        if (k + 3 < K) v.w = s[3];
    }
    __nv_bfloat162 p0 = __floats2bfloat162_rn(v.x, v.y);
    __nv_bfloat162 p1 = __floats2bfloat162_rn(v.z, v.w);
    *reinterpret_cast<uint2*>(dst + (size_t)n * Kp + k) =
        make_uint2(*reinterpret_cast<unsigned*>(&p0), *reinterpret_cast<unsigned*>(&p1));
}

// permute W_hh rows into 8-col gate-interleaved order: p = grp24*24 + gate*8 + joff
__global__ void cvt_perm(const float* __restrict__ src, __nv_bfloat16* __restrict__ dst)
{
    int i4 = blockIdx.x * blockDim.x + threadIdx.x;    // 3HH * HH/4 tasks
    if (i4 >= 3 * HH * (HH / 4)) return;
    int p = i4 / (HH / 4);
    int k = (i4 % (HH / 4)) * 4;
    int group = p / 24, w = p % 24, gate = w >> 3, joff = w & 7;
    int srow = gate * HH + group * 8 + joff;
    float4 v = *reinterpret_cast<const float4*>(src + (size_t)srow * HH + k);
    __nv_bfloat162 p0 = __floats2bfloat162_rn(v.x, v.y);
    __nv_bfloat162 p1 = __floats2bfloat162_rn(v.z, v.w);
    *reinterpret_cast<uint2*>(dst + (size_t)p * KP_H + k) =
        make_uint2(*reinterpret_cast<unsigned*>(&p0), *reinterpret_cast<unsigned*>(&p1));
}

__global__ void init_k()
{
    int i = blockIdx.x * blockDim.x + threadIdx.x;
    if (i < TD * BB) g_sumexp2[i] = 0.f;
}

// ---------------- generic store GEMM (for the two big input-gate GEMMs) ----
template<int NT>
__global__ __launch_bounds__(256) void gemm_tc(
    const __nv_bfloat16* __restrict__ A, const int* __restrict__ gidx,
    const __nv_bfloat16* __restrict__ Bw, const float* __restrict__ bias,
    float* __restrict__ C, int M, int N, int Kp)
{
    constexpr int BN = 16 * NT;
    __shared__ __nv_bfloat16 sm[2][(128 + BN) * STR];

    const int tid  = threadIdx.x;
    const int lane = tid & 31;
    const int wid  = tid >> 5;
    const int grp  = lane >> 2;
    const int tig  = lane & 3;
    const int warp_m = wid & 3;
    const int warp_n = wid >> 2;

    const int rowBase = blockIdx.y * 128;
    const int colBase = blockIdx.x * BN;

    const int ar0 = tid >> 2, ach = tid & 3;
    const int ar1 = ar0 + 64;
    const size_t sr0 = gidx ? (size_t)gidx[rowBase + ar0] : (size_t)(rowBase + ar0);
    const size_t sr1 = gidx ? (size_t)gidx[rowBase + ar1] : (size_t)(rowBase + ar1);
    const __nv_bfloat16* ag0 = A + sr0 * (size_t)Kp + ach * 8;
    const __nv_bfloat16* ag1 = A + sr1 * (size_t)Kp + ach * 8;
    const int aoff0 = ar0 * STR + ach * 8;
    const int aoff1 = ar1 * STR + ach * 8;
    const bool bact = tid < BN * 4;
    const int br = tid >> 2, bch = tid & 3;
    const __nv_bfloat16* bg = Bw + (size_t)(colBase + br) * Kp + bch * 8;
    const int boff = 128 * STR + br * STR + bch * 8;

    float acc[2][NT][4] = {};

    auto issue = [&](int st, int k0) {
        cpa16(&sm[st][aoff0], ag0 + k0);
        cpa16(&sm[st][aoff1], ag1 + k0);
        if (bact) cpa16(&sm[st][boff], bg + k0);
        asm volatile("cp.async.commit_group;\n");
    };

    const int niter = Kp / 32;
    issue(0, 0);
    for (int it = 0; it < niter; it++) {
        if (it + 1 < niter) {
            issue((it + 1) & 1, (it + 1) * 32);
            asm volatile("cp.async.wait_group 1;\n");
        } else {
            asm volatile("cp.async.wait_group 0;\n");
        }
        __syncthreads();
        const __nv_bfloat16* As = sm[it & 1];
        const __nv_bfloat16* Bs = sm[it & 1] + 128 * STR;

        #pragma unroll
        for (int ks = 0; ks < 32; ks += 16) {
            unsigned afr[2][4], bfr[NT][2];
            #pragma unroll
            for (int mt = 0; mt < 2; mt++) {
                const __nv_bfloat16* base =
                    &As[(warp_m * 32 + mt * 16 + grp) * STR + ks + tig * 2];
                afr[mt][0] = *reinterpret_cast<const unsigned*>(base);
                afr[mt][1] = *reinterpret_cast<const unsigned*>(base + 8 * STR);
                afr[mt][2] = *reinterpret_cast<const unsigned*>(base + 8);
                afr[mt][3] = *reinterpret_cast<const unsigned*>(base + 8 * STR + 8);
            }
            #pragma unroll
            for (int nt = 0; nt < NT; nt++) {
                const __nv_bfloat16* base =
                    &Bs[(warp_n * (NT * 8) + nt * 8 + grp) * STR + ks + tig * 2];
                bfr[nt][0] = *reinterpret_cast<const unsigned*>(base);
                bfr[nt][1] = *reinterpret_cast<const unsigned*>(base + 8);
            }
            #pragma unroll
            for (int mt = 0; mt < 2; mt++)
                #pragma unroll
                for (int nt = 0; nt < NT; nt++)
                    mma16816(acc[mt][nt], afr[mt], bfr[nt]);
        }
        __syncthreads();
    }

    #pragma unroll
    for (int mt = 0; mt < 2; mt++) {
        int r0 = rowBase + warp_m * 32 + mt * 16 + grp;
        #pragma unroll
        for (int nt = 0; nt < NT; nt++) {
            int c0 = colBase + warp_n * (NT * 8) + nt * 8 + tig * 2;
            float b0 = bias[c0], b1 = bias[c0 + 1];
            float2 v01 = make_float2(acc[mt][nt][0] + b0, acc[mt][nt][1] + b1);
            float2 v23 = make_float2(acc[mt][nt][2] + b0, acc[mt][nt][3] + b1);
            *reinterpret_cast<float2*>(&C[(size_t)r0 * N + c0]) = v01;
            *reinterpret_cast<float2*>(&C[(size_t)(r0 + 8) * N + c0]) = v23;
        }
    }
}

// ---------------- fused recurrence step: gh GEMM (permuted W) + GRU gate ----
// BM=64, BN=96 (4 j-groups x 3 gates x 8 cols), 8 warps (2m x 4n), 3 stages.
extern __shared__ __nv_bfloat16 dynsm[];

__global__ __launch_bounds__(256) void rec_gru(
    const __nv_bfloat16* __restrict__ A,     // hin bf16 [BB, KP_H]
    const __nv_bfloat16* __restrict__ Wp,    // permuted W_hh [3HH, KP_H]
    const float* __restrict__ b_hh,          // original layout
    const float* __restrict__ gi, int gi_stride,
    const float* __restrict__ hin,
    float* __restrict__ hout,
    __nv_bfloat16* __restrict__ houtbf,
    float* __restrict__ ctx, __nv_bfloat16* __restrict__ ctxbf,
    const int* __restrict__ lengths, int step)
{
    const int SSZ = (64 + 96) * STR;
    const int tid = threadIdx.x, lane = tid & 31, wid = tid >> 5;
    const int grp = lane >> 2, tig = lane & 3;
    const int warp_m = wid & 1;
    const int warp_n = wid >> 1;             // j-group 0..3
    const int rowBase = blockIdx.y * 64;
    const int colBase = blockIdx.x * 96;
    const int jBase = blockIdx.x * 32;

    const int ar = tid >> 2, ach = tid & 3;
    const __nv_bfloat16* ag = A + (size_t)(rowBase + ar) * KP_H + ach * 8;
    const int aoff = ar * STR + ach * 8;
    const int br0 = tid >> 2, bch0 = tid & 3;
    const __nv_bfloat16* bg0 = Wp + (size_t)(colBase + br0) * KP_H + bch0 * 8;
    const int boff0 = 64 * STR + br0 * STR + bch0 * 8;
    const int t2 = tid + 256;
    const int br1 = t2 >> 2, bch1 = t2 & 3;
    const __nv_bfloat16* bg1 = Wp + (size_t)(colBase + br1) * KP_H + bch1 * 8;
    const int boff1 = 64 * STR + br1 * STR + bch1 * 8;
    const bool b2 = tid < 128;

    float acc[2][3][4] = {};

    auto issue = [&](int st, int k0) {
        __nv_bfloat16* s = dynsm + st * SSZ;
        cpa16(s + aoff, ag + k0);
        cpa16(s + boff0, bg0 + k0);
        if (b2) cpa16(s + boff1, bg1 + k0);
        asm volatile("cp.async.commit_group;\n");
    };

    const int niter = KP_H / 32;
    issue(0, 0); issue(1, 32);
    for (int it = 0; it < niter; it++) {
        if (it + 2 < niter) {
            issue((it + 2) % 3, (it + 2) * 32);
            asm volatile("cp.async.wait_group 2;\n");
        } else if (it + 1 < niter) {
            asm volatile("cp.async.wait_group 1;\n");
        } else {
            asm volatile("cp.async.wait_group 0;\n");
        }
        __syncthreads();
        const __nv_bfloat16* As = dynsm + (it % 3) * SSZ;
        const __nv_bfloat16* Bs = As + 64 * STR;

        #pragma unroll
        for (int ks = 0; ks < 32; ks += 16) {
            unsigned afr[2][4], bfr[3][2];
            #pragma unroll
            for (int mt = 0; mt < 2; mt++) {
                const __nv_bfloat16* base =
                    &As[(warp_m * 32 + mt * 16 + grp) * STR + ks + tig * 2];
                afr[mt][0] = *reinterpret_cast<const unsigned*>(base);
                afr[mt][1] = *reinterpret_cast<const unsigned*>(base + 8 * STR);
                afr[mt][2] = *reinterpret_cast<const unsigned*>(base + 8);
                afr[mt][3] = *reinterpret_cast<const unsigned*>(base + 8 * STR + 8);
            }
            #pragma unroll
            for (int nt = 0; nt < 3; nt++) {
                const __nv_bfloat16* base =
                    &Bs[(warp_n * 24 + nt * 8 + grp) * STR + ks + tig * 2];
                bfr[nt][0] = *reinterpret_cast<const unsigned*>(base);
                bfr[nt][1] = *reinterpret_cast<const unsigned*>(base + 8);
            }
            #pragma unroll
            for (int mt = 0; mt < 2; mt++)
                #pragma unroll
                for (int nt = 0; nt < 3; nt++)
                    mma16816(acc[mt][nt], afr[mt], bfr[nt]);
        }
        __syncthreads();
    }

    // ---- fused GRU gate epilogue ----
    const int j = jBase + warp_n * 8 + tig * 2;
    float2 bhr = *reinterpret_cast<const float2*>(b_hh + j);
    float2 bhz = *reinterpret_cast<const float2*>(b_hh + HH + j);
    float2 bhn = *reinterpret_cast<const float2*>(b_hh + 2 * HH + j);

    #pragma unroll
    for (int mt = 0; mt < 2; mt++) {
        #pragma unroll
        for (int h = 0; h < 2; h++) {
            int row = rowBase + warp_m * 32 + mt * 16 + grp + h * 8;
            int q0 = 2 * h;
            const float* gir = gi + (size_t)row * gi_stride;
            float2 gr = *reinterpret_cast<const float2*>(gir + j);
            float2 gz = *reinterpret_cast<const float2*>(gir + HH + j);
            float2 gn = *reinterpret_cast<const float2*>(gir + 2 * HH + j);
            float2 hp = *reinterpret_cast<const float2*>(hin + (size_t)row * HH + j);
            float rx = sigapx(gr.x + acc[mt][0][q0]     + bhr.x);
            float ry = sigapx(gr.y + acc[mt][0][q0 + 1] + bhr.y);
            float zx = sigapx(gz.x + acc[mt][1][q0]     + bhz.x);
            float zy = sigapx(gz.y + acc[mt][1][q0 + 1] + bhz.y);
            float nx = tanhapx(gn.x + rx * (acc[mt][2][q0]     + bhn.x));
            float ny = tanhapx(gn.y + ry * (acc[mt][2][q0 + 1] + bhn.y));
            float ox = (1.f - zx) * nx + zx * hp.x;
            float oy = (1.f - zy) * ny + zy * hp.y;
            *reinterpret_cast<float2*>(hout + (size_t)row * HH + j) = make_float2(ox, oy);
            __nv_bfloat162 pb = __floats2bfloat162_rn(ox, oy);
            *reinterpret_cast<unsigned*>(houtbf + (size_t)row * HH + j) =
                *reinterpret_cast<unsigned*>(&pb);
            if (ctx != nullptr && lengths[row] - 1 == step) {
                *reinterpret_cast<float2*>(ctx + (size_t)row * HH + j) = make_float2(ox, oy);
                *reinterpret_cast<unsigned*>(ctxbf + (size_t)row * HH + j) =
                    *reinterpret_cast<unsigned*>(&pb);
            }
        }
    }
}

// ---------------- FC + fused CE: BM=128, BN=128, NT=8, 3 stages -------------
__global__ __launch_bounds__(256) void fc_ce(
    const __nv_bfloat16* __restrict__ A,
    const __nv_bfloat16* __restrict__ Bw,
    const float* __restrict__ bias,
    const int* __restrict__ targets, int tstep)
{
    const int SSZ = 256 * STR;
    const int tid = threadIdx.x, lane = tid & 31, wid = tid >> 5;
    const int grp = lane >> 2, tig = lane & 3;
    const int warp_m = wid & 3;
    const int warp_n = wid >> 2;
    const int rowBase = blockIdx.y * 128;
    const int colBase = blockIdx.x * 128;

    const int ar0 = tid >> 2, ach = tid & 3;
    const int ar1 = ar0 + 64;
    const __nv_bfloat16* ag0 = A + (size_t)(rowBase + ar0) * KP_H + ach * 8;
    const __nv_bfloat16* ag1 = A + (size_t)(rowBase + ar1) * KP_H + ach * 8;
    const int aoff0 = ar0 * STR + ach * 8;
    const int aoff1 = ar1 * STR + ach * 8;
    const int br0 = tid >> 2, bch = tid & 3;
    const int br1 = br0 + 64;
    const __nv_bfloat16* bg0 = Bw + (size_t)(colBase + br0) * KP_H + bch * 8;
    const __nv_bfloat16* bg1 = Bw + (size_t)(colBase + br1) * KP_H + bch * 8;
    const int boff0 = 128 * STR + br0 * STR + bch * 8;
    const int boff1 = 128 * STR + br1 * STR + bch * 8;

    float acc[2][8][4] = {};

    auto issue = [&](int st, int k0) {
        __nv_bfloat16* s = dynsm + st * SSZ;
        cpa16(s + aoff0, ag0 + k0);
        cpa16(s + aoff1, ag1 + k0);
        cpa16(s + boff0, bg0 + k0);
        cpa16(s + boff1, bg1 + k0);
        asm volatile("cp.async.commit_group;\n");
    };

    const int niter = KP_H / 32;
    issue(0, 0); issue(1, 32);
    for (int it = 0; it < niter; it++) {
        if (it + 2 < niter) {
            issue((it + 2) % 3, (it + 2) * 32);
            asm volatile("cp.async.wait_group 2;\n");
        } else if (it + 1 < niter) {
            asm volatile("cp.async.wait_group 1;\n");
        } else {
            asm volatile("cp.async.wait_group 0;\n");
        }
        __syncthreads();
        const __nv_bfloat16* As = dynsm + (it % 3) * SSZ;
        const __nv_bfloat16* Bs = As + 128 * STR;

        #pragma unroll
        for (int ks = 0; ks < 32; ks += 16) {
            unsigned afr[2][4], bfr[8][2];
            #pragma unroll
            for (int mt = 0; mt < 2; mt++) {
                const __nv_bfloat16* base =
                    &As[(warp_m * 32 + mt * 16 + grp) * STR + ks + tig * 2];
                afr[mt][0] = *reinterpret_cast<const unsigned*>(base);
                afr[mt][1] = *reinterpret_cast<const unsigned*>(base + 8 * STR);
                afr[mt][2] = *reinterpret_cast<const unsigned*>(base + 8);
                afr[mt][3] = *reinterpret_cast<const unsigned*>(base + 8 * STR + 8);
            }
            #pragma unroll
            for (int nt = 0; nt < 8; nt++) {
                const __nv_bfloat16* base =
                    &Bs[(warp_n * 64 + nt * 8 + grp) * STR + ks + tig * 2];
                bfr[nt][0] = *reinterpret_cast<const unsigned*>(base);
                bfr[nt][1] = *reinterpret_cast<const unsigned*>(base + 8);
            }
            #pragma unroll
            for (int mt = 0; mt < 2; mt++)
                #pragma unroll
                for (int nt = 0; nt < 8; nt++)
                    mma16816(acc[mt][nt], afr[mt], bfr[nt]);
        }
        __syncthreads();
    }

    // ---- fused CE epilogue (f16x2 exp2 with offset) ----
    const float kNegOff = -CEOFF * LOG2E;
    #pragma unroll
    for (int mt = 0; mt < 2; mt++) {
        int r0 = rowBase + warp_m * 32 + mt * 16 + grp;
        int tg0 = targets[r0 * TT + tstep + 1];
        int tg1 = targets[(r0 + 8) * TT + tstep + 1];
        __half2 s20 = __float2half2_rn(0.f);
        __half2 s21 = __float2half2_rn(0.f);
        #pragma unroll
        for (int nt = 0; nt < 8; nt++) {
            int c0 = colBase + warp_n * 64 + nt * 8 + tig * 2;
            float2 bb = *reinterpret_cast<const float2*>(bias + c0);
            float v0 = acc[mt][nt][0] + bb.x, v1 = acc[mt][nt][1] + bb.y;
            float v2 = acc[mt][nt][2] + bb.x, v3 = acc[mt][nt][3] + bb.y;
            if (c0 == tg0)     g_tgtlog2[tstep * BB + r0] = v0;
            if (c0 + 1 == tg0) g_tgtlog2[tstep * BB + r0] = v1;
            if (c0 == tg1)     g_tgtlog2[tstep * BB + r0 + 8] = v2;
            if (c0 + 1 == tg1) g_tgtlog2[tstep * BB + r0 + 8] = v3;
            __half2 y0 = __floats2half2_rn(fmaf(v0, LOG2E, kNegOff),
                                           fmaf(v1, LOG2E, kNegOff));
            __half2 y1 = __floats2half2_rn(fmaf(v2, LOG2E, kNegOff),
                                           fmaf(v3, LOG2E, kNegOff));
            s20 = __hadd2(s20, h2exp2(y0));
            s21 = __hadd2(s21, h2exp2(y1));
        }
        float2 f0 = __half22float2(s20);
        float2 f1 = __half22float2(s21);
        float s0 = f0.x + f0.y, s1 = f1.x + f1.y;
        s0 += __shfl_xor_sync(0xffffffffu, s0, 1);
        s0 += __shfl_xor_sync(0xffffffffu, s0, 2);
        s1 += __shfl_xor_sync(0xffffffffu, s1, 1);
        s1 += __shfl_xor_sync(0xffffffffu, s1, 2);
        if (tig == 0) {
            atomicAdd(&g_sumexp2[tstep * BB + r0], s0);
            atomicAdd(&g_sumexp2[tstep * BB + r0 + 8], s1);
        }
    }
}

// ---------------- decoder concat input -------------------------------------
__global__ void build_x(const int* __restrict__ targets,
                        const float* __restrict__ Edec,
                        const float* __restrict__ ctx,
                        __nv_bfloat16* __restrict__ xbf)
{
    int idx = blockIdx.x * blockDim.x + threadIdx.x;
    const int total = BB * TD * KP_X;
    if (idx >= total) return;
    int k = idx % KP_X;
    int rt = idx / KP_X;
    int t = rt % TD, b = rt / TD;
    float v = 0.f;
    if (k < EE) {
        int tok = (t == 0) ? 1 : targets[b * TT + t];
        v = Edec[(size_t)tok * EE + k];
    } else if (k < KX) {
        v = ctx[(size_t)b * HH + (k - EE)];
    }
    xbf[idx] = __float2bfloat16(v);
}

// ---------------- final loss ------------------------------------------------
__global__ void final_loss(const int* __restrict__ targets, float* __restrict__ out)
{
    int b = threadIdx.x;
    __shared__ float sc[256], sk[256];
    float loss = 0.f;
    for (int t = 0; t < TD; t++) {
        float ce = (logf(g_sumexp2[t * BB + b]) + CEOFF) - g_tgtlog2[t * BB + b];
        float mk = (targets[b * TT + t + 1] >= 1) ? 1.f : 0.f;
        sc[b] = ce; sk[b] = mk;
        __syncthreads();
        for (int o = 128; o > 0; o >>= 1) {
            if (b < o) { sc[b] += sc[b + o]; sk[b] += sk[b + o]; }
            __syncthreads();
        }
        if (b == 0) loss += (sc[0] / BB) * (sk[0] / BB);
        __syncthreads();
    }
    if (b == 0) out[0] = loss / TT;
}

// ---------------- launch ----------------------------------------------------
extern "C" void kernel_launch(void* const* d_in, const int* in_sizes, int n_in,
                              void* d_out, int out_size)
{
    const int*   inputs  = (const int*)  d_in[0];
    const int*   targets = (const int*)  d_in[1];
    const int*   lengths = (const int*)  d_in[2];
    const float* h0      = (const float*)d_in[3];
    const float* Eenc    = (const float*)d_in[4];
    const float* Edec    = (const float*)d_in[5];
    const float* W_ih_e  = (const float*)d_in[6];
    const float* W_hh_e  = (const float*)d_in[7];
    const float* b_ih_e  = (const float*)d_in[8];
    const float* b_hh_e  = (const float*)d_in[9];
    const float* W_ih_d  = (const float*)d_in[10];
    const float* W_hh_d  = (const float*)d_in[11];
    const float* b_ih_d  = (const float*)d_in[12];
    const float* b_hh_d  = (const float*)d_in[13];
    const float* W_fc    = (const float*)d_in[14];
    const float* b_fc    = (const float*)d_in[15];
    float* out = (float*)d_out;

    float *p_gi_e, *p_gi_d, *p_hb, *p_ctx;
    __nv_bfloat16 *p_Wihe, *p_WhheP, *p_Wihd, *p_WhhdP, *p_Wfc;
    __nv_bfloat16 *p_hbf, *p_h0bf, *p_ctxbf, *p_xbf, *p_Eencbf;
    cudaGetSymbolAddress((void**)&p_gi_e,   g_gi_e);
    cudaGetSymbolAddress((void**)&p_gi_d,   g_gi_d);
    cudaGetSymbolAddress((void**)&p_hb,     g_hbuf);
    cudaGetSymbolAddress((void**)&p_ctx,    g_ctx);
    cudaGetSymbolAddress((void**)&p_Wihe,   g_Wihe);
    cudaGetSymbolAddress((void**)&p_WhheP,  g_WhheP);
    cudaGetSymbolAddress((void**)&p_Wihd,   g_Wihd);
    cudaGetSymbolAddress((void**)&p_WhhdP,  g_WhhdP);
    cudaGetSymbolAddress((void**)&p_Wfc,    g_Wfc);
    cudaGetSymbolAddress((void**)&p_hbf,    g_hbf);
    cudaGetSymbolAddress((void**)&p_h0bf,   g_h0bf);
    cudaGetSymbolAddress((void**)&p_ctxbf,  g_ctxbf);
    cudaGetSymbolAddress((void**)&p_xbf,    g_xbf);
    cudaGetSymbolAddress((void**)&p_Eencbf, g_Eencbf);
    float* p_h0b = p_hb;
    float* p_h1b = p_hb + (size_t)BB * HH;
    __nv_bfloat16* p_hbf0 = p_hbf;
    __nv_bfloat16* p_hbf1 = p_hbf + (size_t)BB * HH;

    const int recSmem = 3 * (64 + 96) * STR * 2;
    const int fcSmem  = 3 * 256 * STR * 2;
    cudaFuncSetAttribute(rec_gru, cudaFuncAttributeMaxDynamicSharedMemorySize, recSmem);
    cudaFuncSetAttribute(fc_ce,   cudaFuncAttributeMaxDynamicSharedMemorySize, fcSmem);

    init_k<<<(TD * BB + 255) / 256, 256>>>();

    // one-shot conversions
    {
        long long n;
        n = (long long)3 * HH * (KP_E / 4);
        cvt_pad4<<<(unsigned)((n + 255) / 256), 256>>>(W_ih_e, p_Wihe, 3 * HH, EE, KP_E);
        n = (long long)3 * HH * (KP_X / 4);
        cvt_pad4<<<(unsigned)((n + 255) / 256), 256>>>(W_ih_d, p_Wihd, 3 * HH, KX, KP_X);
        n = (long long)VV * (KP_H / 4);
        cvt_pad4<<<(unsigned)((n + 255) / 256), 256>>>(W_fc, p_Wfc, VV, HH, KP_H);
        n = (long long)VIN * (KP_E / 4);
        cvt_pad4<<<(unsigned)((n + 255) / 256), 256>>>(Eenc, p_Eencbf, VIN, EE, KP_E);
        n = (long long)BB * (HH / 4);
        cvt_pad4<<<(unsigned)((n + 255) / 256), 256>>>(h0, p_h0bf, BB, HH, HH);
        n = (long long)3 * HH * (HH / 4);
        cvt_perm<<<(unsigned)((n + 255) / 256), 256>>>(W_hh_e, p_WhheP);
        cvt_perm<<<(unsigned)((n + 255) / 256), 256>>>(W_hh_d, p_WhhdP);
    }

    // Encoder input gates
    gemm_tc<4><<<dim3(3 * HH / 64, (BB * SS) / 128), 256>>>(
        p_Eencbf, inputs, p_Wihe, b_ih_e, p_gi_e, BB * SS, 3 * HH, KP_E);

    // Encoder recurrence (fused)
    const float* hin = h0;
    const __nv_bfloat16* hinbf = p_h0bf;
    for (int s = 0; s < SS; s++) {
        float* hout = (s & 1) ? p_h1b : p_h0b;
        __nv_bfloat16* houtbf = (s & 1) ? p_hbf1 : p_hbf0;
        rec_gru<<<dim3(32, BB / 64), 256, recSmem>>>(
            hinbf, p_WhheP, b_hh_e,
            p_gi_e + (size_t)s * 3 * HH, SS * 3 * HH,
            hin, hout, houtbf, p_ctx, p_ctxbf, lengths, s);
        hin = hout; hinbf = houtbf;
    }

    // Decoder input gates
    build_x<<<(BB * TD * KP_X + 255) / 256, 256>>>(targets, Edec, p_ctx, p_xbf);
    gemm_tc<4><<<dim3(3 * HH / 64, (BB * TD) / 128), 256>>>(
        p_xbf, nullptr, p_Wihd, b_ih_d, p_gi_d, BB * TD, 3 * HH, KP_X);

    // Decoder recurrence + fused FC/CE
    hin = p_ctx; hinbf = p_ctxbf;
    for (int t = 0; t < TD; t++) {
        float* hout = (t & 1) ? p_h1b : p_h0b;
        __nv_bfloat16* houtbf = (t & 1) ? p_hbf1 : p_hbf0;
        rec_gru<<<dim3(32, BB / 64), 256, recSmem>>>(
            hinbf, p_WhhdP, b_hh_d,
            p_gi_d + (size_t)t * 3 * HH, TD * 3 * HH,
            hin, hout, houtbf, nullptr, nullptr, nullptr, -1);
        hin = hout; hinbf = houtbf;
        fc_ce<<<dim3(VV / 128, BB / 128), 256, fcSmem>>>(
            houtbf, p_Wfc, b_fc, targets, t);
    }

    final_loss<<<1, 256>>>(targets, out);
}

// round 17
// speedup vs baseline: 7.2463x; 1.1131x over previous
#include <cuda_runtime.h>
#include <cuda_bf16.h>
#include <cuda_fp16.h>
#include <stdint.h>
#include <math.h>

#define BB   256
#define SS   64
#define TT   20
#define EE   100
#define HH   1024
#define VV   32000
#define VIN  32000
#define TD   (TT-1)
#define KX   (EE+HH)

#define KP_E 128
#define KP_H 1024
#define KP_X 1152

#define STR 56          // smem row stride (bf16 elems) = 112B, conflict-free
#define CEOFF 4.0f      // exp offset for f16 sumexp
#define LOG2E 1.4426950408889634f

// ---------------- scratch ---------------------------------------------------
__device__ float g_gi_e[(size_t)BB*SS*3*HH];
__device__ float g_gi_d[(size_t)BB*TD*3*HH];
__device__ float g_hbuf[2][(size_t)BB*HH];
__device__ float g_ctx[(size_t)BB*HH];
__device__ float g_sumexp2[(size_t)TD*BB];
__device__ float g_tgtlog2[(size_t)TD*BB];

__device__ __nv_bfloat16 g_hbf[2][(size_t)BB*HH];
__device__ __nv_bfloat16 g_h0bf[(size_t)BB*HH];
__device__ __nv_bfloat16 g_ctxbf[(size_t)BB*HH];
__device__ __nv_bfloat16 g_hdecbf[(size_t)TD*BB*HH];   // all decoder hidden states
__device__ __nv_bfloat16 g_xbf[(size_t)BB*TD*KP_X];
__device__ __nv_bfloat16 g_Eencbf[(size_t)VIN*KP_E];
__device__ __nv_bfloat16 g_Wihe[(size_t)3*HH*KP_E];
__device__ __nv_bfloat16 g_WhheP[(size_t)3*HH*KP_H];   // gate-interleave permuted
__device__ __nv_bfloat16 g_Wihd[(size_t)3*HH*KP_X];
__device__ __nv_bfloat16 g_WhhdP[(size_t)3*HH*KP_H];   // gate-interleave permuted
__device__ __nv_bfloat16 g_Wfc [(size_t)VV*KP_H];

// ---------------- helpers ---------------------------------------------------
__device__ __forceinline__ void cpa16(void* s, const void* g)
{
    unsigned sa = (unsigned)__cvta_generic_to_shared(s);
    asm volatile("cp.async.cg.shared.global [%0], [%1], 16;\n" :: "r"(sa), "l"(g));
}
__device__ __forceinline__ void mma16816(float* c, const unsigned* a, const unsigned* b)
{
    asm volatile(
        "mma.sync.aligned.m16n8k16.row.col.f32.bf16.bf16.f32 "
        "{%0,%1,%2,%3}, {%4,%5,%6,%7}, {%8,%9}, {%0,%1,%2,%3};\n"
        : "+f"(c[0]), "+f"(c[1]), "+f"(c[2]), "+f"(c[3])
        : "r"(a[0]), "r"(a[1]), "r"(a[2]), "r"(a[3]), "r"(b[0]), "r"(b[1]));
}
__device__ __forceinline__ float tanhapx(float x)
{
    float y; asm("tanh.approx.f32 %0, %1;" : "=f"(y) : "f"(x)); return y;
}
__device__ __forceinline__ float sigapx(float x) { return 0.5f * tanhapx(0.5f * x) + 0.5f; }

// ---------------- conversions ----------------------------------------------
__global__ void cvt_pad4(const float* __restrict__ src,
                         __nv_bfloat16* __restrict__ dst,
                         int N, int K, int Kp)
{
    long long i4 = (long long)blockIdx.x * blockDim.x + threadIdx.x;
    long long total = (long long)N * (Kp / 4);
    if (i4 >= total) return;
    int n = (int)(i4 / (Kp / 4));
    int k = (int)(i4 % (Kp / 4)) * 4;
    const float* s = src + (size_t)n * K + k;
    float4 v = make_float4(0.f, 0.f, 0.f, 0.f);
    if (k + 3 < K) v = *reinterpret_cast<const float4*>(s);
    else {
        if (k     < K) v.x = s[0];
        if (k + 1 < K) v.y = s[1];
        if (k + 2 < K) v.z = s[2];
        if (k + 3 < K) v.w = s[3];
    }
    __nv_bfloat162 p0 = __floats2bfloat162_rn(v.x, v.y);
    __nv_bfloat162 p1 = __floats2bfloat162_rn(v.z, v.w);
    *reinterpret_cast<uint2*>(dst + (size_t)n * Kp + k) =
        make_uint2(*reinterpret_cast<unsigned*>(&p0), *reinterpret_cast<unsigned*>(&p1));
}

__global__ void cvt_perm(const float* __restrict__ src, __nv_bfloat16* __restrict__ dst)
{
    int i4 = blockIdx.x * blockDim.x + threadIdx.x;
    if (i4 >= 3 * HH * (HH / 4)) return;
    int p = i4 / (HH / 4);
    int k = (i4 % (HH / 4)) * 4;
    int group = p / 24, w = p % 24, gate = w >> 3, joff = w & 7;
    int srow = gate * HH + group * 8 + joff;
    float4 v = *reinterpret_cast<const float4*>(src + (size_t)srow * HH + k);
    __nv_bfloat162 p0 = __floats2bfloat162_rn(v.x, v.y);
    __nv_bfloat162 p1 = __floats2bfloat162_rn(v.z, v.w);
    *reinterpret_cast<uint2*>(dst + (size_t)p * KP_H + k) =
        make_uint2(*reinterpret_cast<unsigned*>(&p0), *reinterpret_cast<unsigned*>(&p1));
}

__global__ void init_k()
{
    int i = blockIdx.x * blockDim.x + threadIdx.x;
    if (i < TD * BB) g_sumexp2[i] = 0.f;
}

// ---------------- HMMA GEMM for input-gate GEMMs ----------------------------
template<int NT>
__global__ __launch_bounds__(256) void gemm_tc(
    const __nv_bfloat16* __restrict__ A, const int* __restrict__ gidx,
    const __nv_bfloat16* __restrict__ Bw, const float* __restrict__ bias,
    float* __restrict__ C, int M, int N, int Kp)
{
    constexpr int BN = 16 * NT;
    __shared__ __nv_bfloat16 sm[2][(128 + BN) * STR];

    const int tid  = threadIdx.x;
    const int lane = tid & 31;
    const int wid  = tid >> 5;
    const int grp  = lane >> 2;
    const int tig  = lane & 3;
    const int warp_m = wid & 3;
    const int warp_n = wid >> 2;

    const int rowBase = blockIdx.y * 128;
    const int colBase = blockIdx.x * BN;

    const int ar0 = tid >> 2, ach = tid & 3;
    const int ar1 = ar0 + 64;
    const size_t sr0 = gidx ? (size_t)gidx[rowBase + ar0] : (size_t)(rowBase + ar0);
    const size_t sr1 = gidx ? (size_t)gidx[rowBase + ar1] : (size_t)(rowBase + ar1);
    const __nv_bfloat16* ag0 = A + sr0 * (size_t)Kp + ach * 8;
    const __nv_bfloat16* ag1 = A + sr1 * (size_t)Kp + ach * 8;
    const int aoff0 = ar0 * STR + ach * 8;
    const int aoff1 = ar1 * STR + ach * 8;
    const bool bact = tid < BN * 4;
    const int br = tid >> 2, bch = tid & 3;
    const __nv_bfloat16* bg = Bw + (size_t)(colBase + br) * Kp + bch * 8;
    const int boff = 128 * STR + br * STR + bch * 8;

    float acc[2][NT][4] = {};

    auto issue = [&](int st, int k0) {
        cpa16(&sm[st][aoff0], ag0 + k0);
        cpa16(&sm[st][aoff1], ag1 + k0);
        if (bact) cpa16(&sm[st][boff], bg + k0);
        asm volatile("cp.async.commit_group;\n");
    };

    const int niter = Kp / 32;
    issue(0, 0);
    for (int it = 0; it < niter; it++) {
        if (it + 1 < niter) {
            issue((it + 1) & 1, (it + 1) * 32);
            asm volatile("cp.async.wait_group 1;\n");
        } else {
            asm volatile("cp.async.wait_group 0;\n");
        }
        __syncthreads();
        const __nv_bfloat16* As = sm[it & 1];
        const __nv_bfloat16* Bs = sm[it & 1] + 128 * STR;

        #pragma unroll
        for (int ks = 0; ks < 32; ks += 16) {
            unsigned afr[2][4], bfr[NT][2];
            #pragma unroll
            for (int mt = 0; mt < 2; mt++) {
                const __nv_bfloat16* base =
                    &As[(warp_m * 32 + mt * 16 + grp) * STR + ks + tig * 2];
                afr[mt][0] = *reinterpret_cast<const unsigned*>(base);
                afr[mt][1] = *reinterpret_cast<const unsigned*>(base + 8 * STR);
                afr[mt][2] = *reinterpret_cast<const unsigned*>(base + 8);
                afr[mt][3] = *reinterpret_cast<const unsigned*>(base + 8 * STR + 8);
            }
            #pragma unroll
            for (int nt = 0; nt < NT; nt++) {
                const __nv_bfloat16* base =
                    &Bs[(warp_n * (NT * 8) + nt * 8 + grp) * STR + ks + tig * 2];
                bfr[nt][0] = *reinterpret_cast<const unsigned*>(base);
                bfr[nt][1] = *reinterpret_cast<const unsigned*>(base + 8);
            }
            #pragma unroll
            for (int mt = 0; mt < 2; mt++)
                #pragma unroll
                for (int nt = 0; nt < NT; nt++)
                    mma16816(acc[mt][nt], afr[mt], bfr[nt]);
        }
        __syncthreads();
    }

    #pragma unroll
    for (int mt = 0; mt < 2; mt++) {
        int r0 = rowBase + warp_m * 32 + mt * 16 + grp;
        #pragma unroll
        for (int nt = 0; nt < NT; nt++) {
            int c0 = colBase + warp_n * (NT * 8) + nt * 8 + tig * 2;
            float b0 = bias[c0], b1 = bias[c0 + 1];
            float2 v01 = make_float2(acc[mt][nt][0] + b0, acc[mt][nt][1] + b1);
            float2 v23 = make_float2(acc[mt][nt][2] + b0, acc[mt][nt][3] + b1);
            *reinterpret_cast<float2*>(&C[(size_t)r0 * N + c0]) = v01;
            *reinterpret_cast<float2*>(&C[(size_t)(r0 + 8) * N + c0]) = v23;
        }
    }
}

// ---------------- fused recurrence step (HMMA + GRU gate) -------------------
extern __shared__ __align__(1024) __nv_bfloat16 dynsm[];

__global__ __launch_bounds__(256) void rec_gru(
    const __nv_bfloat16* __restrict__ A,
    const __nv_bfloat16* __restrict__ Wp,
    const float* __restrict__ b_hh,
    const float* __restrict__ gi, int gi_stride,
    const float* __restrict__ hin,
    float* __restrict__ hout,
    __nv_bfloat16* __restrict__ houtbf,
    float* __restrict__ ctx, __nv_bfloat16* __restrict__ ctxbf,
    const int* __restrict__ lengths, int step)
{
    const int SSZ = (64 + 96) * STR;
    const int tid = threadIdx.x, lane = tid & 31, wid = tid >> 5;
    const int grp = lane >> 2, tig = lane & 3;
    const int warp_m = wid & 1;
    const int warp_n = wid >> 1;
    const int rowBase = blockIdx.y * 64;
    const int colBase = blockIdx.x * 96;
    const int jBase = blockIdx.x * 32;

    const int ar = tid >> 2, ach = tid & 3;
    const __nv_bfloat16* ag = A + (size_t)(rowBase + ar) * KP_H + ach * 8;
    const int aoff = ar * STR + ach * 8;
    const int br0 = tid >> 2, bch0 = tid & 3;
    const __nv_bfloat16* bg0 = Wp + (size_t)(colBase + br0) * KP_H + bch0 * 8;
    const int boff0 = 64 * STR + br0 * STR + bch0 * 8;
    const int t2 = tid + 256;
    const int br1 = t2 >> 2, bch1 = t2 & 3;
    const __nv_bfloat16* bg1 = Wp + (size_t)(colBase + br1) * KP_H + bch1 * 8;
    const int boff1 = 64 * STR + br1 * STR + bch1 * 8;
    const bool b2 = tid < 128;

    float acc[2][3][4] = {};

    auto issue = [&](int st, int k0) {
        __nv_bfloat16* s = dynsm + st * SSZ;
        cpa16(s + aoff, ag + k0);
        cpa16(s + boff0, bg0 + k0);
        if (b2) cpa16(s + boff1, bg1 + k0);
        asm volatile("cp.async.commit_group;\n");
    };

    const int niter = KP_H / 32;
    issue(0, 0); issue(1, 32);
    for (int it = 0; it < niter; it++) {
        if (it + 2 < niter) {
            issue((it + 2) % 3, (it + 2) * 32);
            asm volatile("cp.async.wait_group 2;\n");
        } else if (it + 1 < niter) {
            asm volatile("cp.async.wait_group 1;\n");
        } else {
            asm volatile("cp.async.wait_group 0;\n");
        }
        __syncthreads();
        const __nv_bfloat16* As = dynsm + (it % 3) * SSZ;
        const __nv_bfloat16* Bs = As + 64 * STR;

        #pragma unroll
        for (int ks = 0; ks < 32; ks += 16) {
            unsigned afr[2][4], bfr[3][2];
            #pragma unroll
            for (int mt = 0; mt < 2; mt++) {
                const __nv_bfloat16* base =
                    &As[(warp_m * 32 + mt * 16 + grp) * STR + ks + tig * 2];
                afr[mt][0] = *reinterpret_cast<const unsigned*>(base);
                afr[mt][1] = *reinterpret_cast<const unsigned*>(base + 8 * STR);
                afr[mt][2] = *reinterpret_cast<const unsigned*>(base + 8);
                afr[mt][3] = *reinterpret_cast<const unsigned*>(base + 8 * STR + 8);
            }
            #pragma unroll
            for (int nt = 0; nt < 3; nt++) {
                const __nv_bfloat16* base =
                    &Bs[(warp_n * 24 + nt * 8 + grp) * STR + ks + tig * 2];
                bfr[nt][0] = *reinterpret_cast<const unsigned*>(base);
                bfr[nt][1] = *reinterpret_cast<const unsigned*>(base + 8);
            }
            #pragma unroll
            for (int mt = 0; mt < 2; mt++)
                #pragma unroll
                for (int nt = 0; nt < 3; nt++)
                    mma16816(acc[mt][nt], afr[mt], bfr[nt]);
        }
        __syncthreads();
    }

    const int j = jBase + warp_n * 8 + tig * 2;
    float2 bhr = *reinterpret_cast<const float2*>(b_hh + j);
    float2 bhz = *reinterpret_cast<const float2*>(b_hh + HH + j);
    float2 bhn = *reinterpret_cast<const float2*>(b_hh + 2 * HH + j);

    #pragma unroll
    for (int mt = 0; mt < 2; mt++) {
        #pragma unroll
        for (int h = 0; h < 2; h++) {
            int row = rowBase + warp_m * 32 + mt * 16 + grp + h * 8;
            int q0 = 2 * h;
            const float* gir = gi + (size_t)row * gi_stride;
            float2 gr = *reinterpret_cast<const float2*>(gir + j);
            float2 gz = *reinterpret_cast<const float2*>(gir + HH + j);
            float2 gn = *reinterpret_cast<const float2*>(gir + 2 * HH + j);
            float2 hp = *reinterpret_cast<const float2*>(hin + (size_t)row * HH + j);
            float rx = sigapx(gr.x + acc[mt][0][q0]     + bhr.x);
            float ry = sigapx(gr.y + acc[mt][0][q0 + 1] + bhr.y);
            float zx = sigapx(gz.x + acc[mt][1][q0]     + bhz.x);
            float zy = sigapx(gz.y + acc[mt][1][q0 + 1] + bhz.y);
            float nx = tanhapx(gn.x + rx * (acc[mt][2][q0]     + bhn.x));
            float ny = tanhapx(gn.y + ry * (acc[mt][2][q0 + 1] + bhn.y));
            float ox = (1.f - zx) * nx + zx * hp.x;
            float oy = (1.f - zy) * ny + zy * hp.y;
            *reinterpret_cast<float2*>(hout + (size_t)row * HH + j) = make_float2(ox, oy);
            __nv_bfloat162 pb = __floats2bfloat162_rn(ox, oy);
            *reinterpret_cast<unsigned*>(houtbf + (size_t)row * HH + j) =
                *reinterpret_cast<unsigned*>(&pb);
            if (ctx != nullptr && lengths[row] - 1 == step) {
                *reinterpret_cast<float2*>(ctx + (size_t)row * HH + j) = make_float2(ox, oy);
                *reinterpret_cast<unsigned*>(ctxbf + (size_t)row * HH + j) =
                    *reinterpret_cast<unsigned*>(&pb);
            }
        }
    }
}

// ---------------- batched FC + fused CE (HMMA, one launch over TD*BB) -------
// A: [TD*BB, KP_H] bf16 decoder hidden states. Row gr = t*BB + b.
__global__ __launch_bounds__(256) void fc_ce(
    const __nv_bfloat16* __restrict__ A,
    const __nv_bfloat16* __restrict__ Bw,
    const float* __restrict__ bias,
    const int* __restrict__ targets)
{
    const int SSZ = 256 * STR;
    const int tid = threadIdx.x, lane = tid & 31, wid = tid >> 5;
    const int grp = lane >> 2, tig = lane & 3;
    const int warp_m = wid & 3;
    const int warp_n = wid >> 2;
    const int rowBase = blockIdx.y * 128;
    const int colBase = blockIdx.x * 128;

    const int ar0 = tid >> 2, ach = tid & 3;
    const int ar1 = ar0 + 64;
    const __nv_bfloat16* ag0 = A + (size_t)(rowBase + ar0) * KP_H + ach * 8;
    const __nv_bfloat16* ag1 = A + (size_t)(rowBase + ar1) * KP_H + ach * 8;
    const int aoff0 = ar0 * STR + ach * 8;
    const int aoff1 = ar1 * STR + ach * 8;
    const int br0 = tid >> 2, bch = tid & 3;
    const int br1 = br0 + 64;
    const __nv_bfloat16* bg0 = Bw + (size_t)(colBase + br0) * KP_H + bch * 8;
    const __nv_bfloat16* bg1 = Bw + (size_t)(colBase + br1) * KP_H + bch * 8;
    const int boff0 = 128 * STR + br0 * STR + bch * 8;
    const int boff1 = 128 * STR + br1 * STR + bch * 8;

    float acc[2][8][4] = {};

    auto issue = [&](int st, int k0) {
        __nv_bfloat16* s = dynsm + st * SSZ;
        cpa16(s + aoff0, ag0 + k0);
        cpa16(s + aoff1, ag1 + k0);
        cpa16(s + boff0, bg0 + k0);
        cpa16(s + boff1, bg1 + k0);
        asm volatile("cp.async.commit_group;\n");
    };

    const int niter = KP_H / 32;
    issue(0, 0); issue(1, 32);
    for (int it = 0; it < niter; it++) {
        if (it + 2 < niter) {
            issue((it + 2) % 3, (it + 2) * 32);
            asm volatile("cp.async.wait_group 2;\n");
        } else if (it + 1 < niter) {
            asm volatile("cp.async.wait_group 1;\n");
        } else {
            asm volatile("cp.async.wait_group 0;\n");
        }
        __syncthreads();
        const __nv_bfloat16* As = dynsm + (it % 3) * SSZ;
        const __nv_bfloat16* Bs = As + 128 * STR;

        #pragma unroll
        for (int ks = 0; ks < 32; ks += 16) {
            unsigned afr[2][4], bfr[8][2];
            #pragma unroll
            for (int mt = 0; mt < 2; mt++) {
                const __nv_bfloat16* base =
                    &As[(warp_m * 32 + mt * 16 + grp) * STR + ks + tig * 2];
                afr[mt][0] = *reinterpret_cast<const unsigned*>(base);
                afr[mt][1] = *reinterpret_cast<const unsigned*>(base + 8 * STR);
                afr[mt][2] = *reinterpret_cast<const unsigned*>(base + 8);
                afr[mt][3] = *reinterpret_cast<const unsigned*>(base + 8 * STR + 8);
            }
            #pragma unroll
            for (int nt = 0; nt < 8; nt++) {
                const __nv_bfloat16* base =
                    &Bs[(warp_n * 64 + nt * 8 + grp) * STR + ks + tig * 2];
                bfr[nt][0] = *reinterpret_cast<const unsigned*>(base);
                bfr[nt][1] = *reinterpret_cast<const unsigned*>(base + 8);
            }
            #pragma unroll
            for (int mt = 0; mt < 2; mt++)
                #pragma unroll
                for (int nt = 0; nt < 8; nt++)
                    mma16816(acc[mt][nt], afr[mt], bfr[nt]);
        }
        __syncthreads();
    }

    // ---- fused CE epilogue (f16x2 exp2 with offset) ----
    const float kNegOff = -CEOFF * LOG2E;
    #pragma unroll
    for (int mt = 0; mt < 2; mt++) {
        int r0 = rowBase + warp_m * 32 + mt * 16 + grp;   // gr = t*BB + b
        int t0 = r0 / BB,       b0_ = r0 % BB;
        int t1 = (r0 + 8) / BB, b1_ = (r0 + 8) % BB;
        int tg0 = targets[b0_ * TT + t0 + 1];
        int tg1 = targets[b1_ * TT + t1 + 1];
        __half2 s20 = __float2half2_rn(0.f);
        __half2 s21 = __float2half2_rn(0.f);
        #pragma unroll
        for (int nt = 0; nt < 8; nt++) {
            int c0 = colBase + warp_n * 64 + nt * 8 + tig * 2;
            float2 bb = *reinterpret_cast<const float2*>(bias + c0);
            float v0 = acc[mt][nt][0] + bb.x, v1 = acc[mt][nt][1] + bb.y;
            float v2 = acc[mt][nt][2] + bb.x, v3 = acc[mt][nt][3] + bb.y;
            if (c0 == tg0)     g_tgtlog2[r0] = v0;
            if (c0 + 1 == tg0) g_tgtlog2[r0] = v1;
            if (c0 == tg1)     g_tgtlog2[r0 + 8] = v2;
            if (c0 + 1 == tg1) g_tgtlog2[r0 + 8] = v3;
            __half2 y0 = __floats2half2_rn(fmaf(v0, LOG2E, kNegOff),
                                           fmaf(v1, LOG2E, kNegOff));
            __half2 y1 = __floats2half2_rn(fmaf(v2, LOG2E, kNegOff),
                                           fmaf(v3, LOG2E, kNegOff));
            s20 = __hadd2(s20, h2exp2(y0));
            s21 = __hadd2(s21, h2exp2(y1));
        }
        float2 f0 = __half22float2(s20);
        float2 f1 = __half22float2(s21);
        float s0 = f0.x + f0.y, s1 = f1.x + f1.y;
        s0 += __shfl_xor_sync(0xffffffffu, s0, 1);
        s0 += __shfl_xor_sync(0xffffffffu, s0, 2);
        s1 += __shfl_xor_sync(0xffffffffu, s1, 1);
        s1 += __shfl_xor_sync(0xffffffffu, s1, 2);
        if (tig == 0) {
            atomicAdd(&g_sumexp2[r0], s0);
            atomicAdd(&g_sumexp2[r0 + 8], s1);
        }
    }
}

// ---------------- decoder concat input -------------------------------------
__global__ void build_x(const int* __restrict__ targets,
                        const float* __restrict__ Edec,
                        const float* __restrict__ ctx,
                        __nv_bfloat16* __restrict__ xbf)
{
    int idx = blockIdx.x * blockDim.x + threadIdx.x;
    const int total = BB * TD * KP_X;
    if (idx >= total) return;
    int k = idx % KP_X;
    int rt = idx / KP_X;
    int t = rt % TD, b = rt / TD;
    float v = 0.f;
    if (k < EE) {
        int tok = (t == 0) ? 1 : targets[b * TT + t];
        v = Edec[(size_t)tok * EE + k];
    } else if (k < KX) {
        v = ctx[(size_t)b * HH + (k - EE)];
    }
    xbf[idx] = __float2bfloat16(v);
}

// ---------------- final loss ------------------------------------------------
__global__ void final_loss(const int* __restrict__ targets, float* __restrict__ out)
{
    int b = threadIdx.x;
    __shared__ float sc[256], sk[256];
    float loss = 0.f;
    for (int t = 0; t < TD; t++) {
        float ce = (logf(g_sumexp2[t * BB + b]) + CEOFF) - g_tgtlog2[t * BB + b];
        float mk = (targets[b * TT + t + 1] >= 1) ? 1.f : 0.f;
        sc[b] = ce; sk[b] = mk;
        __syncthreads();
        for (int o = 128; o > 0; o >>= 1) {
            if (b < o) { sc[b] += sc[b + o]; sk[b] += sk[b + o]; }
            __syncthreads();
        }
        if (b == 0) loss += (sc[0] / BB) * (sk[0] / BB);
        __syncthreads();
    }
    if (b == 0) out[0] = loss / TT;
}

// ---------------- launch ----------------------------------------------------
extern "C" void kernel_launch(void* const* d_in, const int* in_sizes, int n_in,
                              void* d_out, int out_size)
{
    const int*   inputs  = (const int*)  d_in[0];
    const int*   targets = (const int*)  d_in[1];
    const int*   lengths = (const int*)  d_in[2];
    const float* h0      = (const float*)d_in[3];
    const float* Eenc    = (const float*)d_in[4];
    const float* Edec    = (const float*)d_in[5];
    const float* W_ih_e  = (const float*)d_in[6];
    const float* W_hh_e  = (const float*)d_in[7];
    const float* b_ih_e  = (const float*)d_in[8];
    const float* b_hh_e  = (const float*)d_in[9];
    const float* W_ih_d  = (const float*)d_in[10];
    const float* W_hh_d  = (const float*)d_in[11];
    const float* b_ih_d  = (const float*)d_in[12];
    const float* b_hh_d  = (const float*)d_in[13];
    const float* W_fc    = (const float*)d_in[14];
    const float* b_fc    = (const float*)d_in[15];
    float* out = (float*)d_out;

    float *p_gi_e, *p_gi_d, *p_hb, *p_ctx;
    __nv_bfloat16 *p_Wihe, *p_WhheP, *p_Wihd, *p_WhhdP, *p_Wfc;
    __nv_bfloat16 *p_hbf, *p_h0bf, *p_ctxbf, *p_xbf, *p_Eencbf, *p_hdec;
    cudaGetSymbolAddress((void**)&p_gi_e,   g_gi_e);
    cudaGetSymbolAddress((void**)&p_gi_d,   g_gi_d);
    cudaGetSymbolAddress((void**)&p_hb,     g_hbuf);
    cudaGetSymbolAddress((void**)&p_ctx,    g_ctx);
    cudaGetSymbolAddress((void**)&p_Wihe,   g_Wihe);
    cudaGetSymbolAddress((void**)&p_WhheP,  g_WhheP);
    cudaGetSymbolAddress((void**)&p_Wihd,   g_Wihd);
    cudaGetSymbolAddress((void**)&p_WhhdP,  g_WhhdP);
    cudaGetSymbolAddress((void**)&p_Wfc,    g_Wfc);
    cudaGetSymbolAddress((void**)&p_hbf,    g_hbf);
    cudaGetSymbolAddress((void**)&p_h0bf,   g_h0bf);
    cudaGetSymbolAddress((void**)&p_ctxbf,  g_ctxbf);
    cudaGetSymbolAddress((void**)&p_xbf,    g_xbf);
    cudaGetSymbolAddress((void**)&p_Eencbf, g_Eencbf);
    cudaGetSymbolAddress((void**)&p_hdec,   g_hdecbf);
    float* p_h0b = p_hb;
    float* p_h1b = p_hb + (size_t)BB * HH;
    __nv_bfloat16* p_hbf0 = p_hbf;
    __nv_bfloat16* p_hbf1 = p_hbf + (size_t)BB * HH;

    const int recSmem = 3 * (64 + 96) * STR * 2;
    const int fcSmem  = 3 * 256 * STR * 2;
    cudaFuncSetAttribute(rec_gru, cudaFuncAttributeMaxDynamicSharedMemorySize, recSmem);
    cudaFuncSetAttribute(fc_ce,   cudaFuncAttributeMaxDynamicSharedMemorySize, fcSmem);

    init_k<<<(TD * BB + 255) / 256, 256>>>();

    // one-shot conversions
    {
        long long n;
        n = (long long)3 * HH * (KP_E / 4);
        cvt_pad4<<<(unsigned)((n + 255) / 256), 256>>>(W_ih_e, p_Wihe, 3 * HH, EE, KP_E);
        n = (long long)3 * HH * (KP_X / 4);
        cvt_pad4<<<(unsigned)((n + 255) / 256), 256>>>(W_ih_d, p_Wihd, 3 * HH, KX, KP_X);
        n = (long long)VV * (KP_H / 4);
        cvt_pad4<<<(unsigned)((n + 255) / 256), 256>>>(W_fc, p_Wfc, VV, HH, KP_H);
        n = (long long)VIN * (KP_E / 4);
        cvt_pad4<<<(unsigned)((n + 255) / 256), 256>>>(Eenc, p_Eencbf, VIN, EE, KP_E);
        n = (long long)BB * (HH / 4);
        cvt_pad4<<<(unsigned)((n + 255) / 256), 256>>>(h0, p_h0bf, BB, HH, HH);
        n = (long long)3 * HH * (HH / 4);
        cvt_perm<<<(unsigned)((n + 255) / 256), 256>>>(W_hh_e, p_WhheP);
        cvt_perm<<<(unsigned)((n + 255) / 256), 256>>>(W_hh_d, p_WhhdP);
    }

    // Encoder input gates
    gemm_tc<4><<<dim3(3 * HH / 64, (BB * SS) / 128), 256>>>(
        p_Eencbf, inputs, p_Wihe, b_ih_e, p_gi_e, BB * SS, 3 * HH, KP_E);

    // Encoder recurrence (fused)
    const float* hin = h0;
    const __nv_bfloat16* hinbf = p_h0bf;
    for (int s = 0; s < SS; s++) {
        float* hout = (s & 1) ? p_h1b : p_h0b;
        __nv_bfloat16* houtbf = (s & 1) ? p_hbf1 : p_hbf0;
        rec_gru<<<dim3(32, BB / 64), 256, recSmem>>>(
            hinbf, p_WhheP, b_hh_e,
            p_gi_e + (size_t)s * 3 * HH, SS * 3 * HH,
            hin, hout, houtbf, p_ctx, p_ctxbf, lengths, s);
        hin = hout; hinbf = houtbf;
    }

    // Decoder input gates
    build_x<<<(BB * TD * KP_X + 255) / 256, 256>>>(targets, Edec, p_ctx, p_xbf);
    gemm_tc<4><<<dim3(3 * HH / 64, (BB * TD) / 128), 256>>>(
        p_xbf, nullptr, p_Wihd, b_ih_d, p_gi_d, BB * TD, 3 * HH, KP_X);

    // Decoder recurrence (all steps; bf16 states land in g_hdecbf)
    hin = p_ctx; hinbf = p_ctxbf;
    for (int t = 0; t < TD; t++) {
        float* hout = (t & 1) ? p_h1b : p_h0b;
        __nv_bfloat16* houtbf = p_hdec + (size_t)t * BB * HH;
        rec_gru<<<dim3(32, BB / 64), 256, recSmem>>>(
            hinbf, p_WhhdP, b_hh_d,
            p_gi_d + (size_t)t * 3 * HH, TD * 3 * HH,
            hin, hout, houtbf, nullptr, nullptr, nullptr, -1);
        hin = hout; hinbf = houtbf;
    }

    // ONE batched FC + CE over all decoder steps
    fc_ce<<<dim3(VV / 128, (TD * BB) / 128), 256, fcSmem>>>(
        p_hdec, p_Wfc, b_fc, targets);

    final_loss<<<1, 256>>>(targets, out);
}